// round 3
// baseline (speedup 1.0000x reference)
#include <cuda_runtime.h>
#include <cuda_bf16.h>
#include <math.h>

#define BB   128
#define PP   196
#define ENC  2048
#define EMB  512
#define DEC  512
#define ATT  512
#define VV   10000
#define TT   20
#define TS   19      // T-1

// ---------------- scratch (device globals, no allocation) ----------------
__device__ float g_mean[BB * ENC];
__device__ float g_h[BB * DEC];
__device__ float g_c[BB * DEC];
__device__ float g_encproj[(size_t)BB * PP * ATT];   // 51.4 MB
__device__ float g_dproj[BB * ATT];
__device__ float g_scores[BB * PP];
__device__ float g_alpha[BB * PP];
__device__ float g_context[BB * ENC];
__device__ float g_gate[BB * ENC];
__device__ float g_x[BB * (EMB + ENC)];
__device__ float g_gates[BB * 4 * DEC];

__device__ __forceinline__ float sigmf(float x) { return 1.f / (1.f + expf(-x)); }

// ---------------- generic 64x64 tiled SGEMM (4x4 micro), guarded ----------
// C[M,N](ldc) = act( A[M,K] @ B[K,N] + bias[N] (+ C if ACCUM) )
// K must be a multiple of 16 and 16B-aligned rows (true for all uses here).
template <int ACT, int ACCUM>
__global__ void gemm64_k(const float* __restrict__ A, const float* __restrict__ Bm,
                         const float* __restrict__ bias, float* __restrict__ C,
                         int M, int N, int K, int ldc)
{
    __shared__ float As[16][64];
    __shared__ float Bs[16][64];
    const int bm = blockIdx.y * 64;
    const int bn = blockIdx.x * 64;
    const int tid = threadIdx.x;          // 0..255
    const int tx = tid & 15;
    const int ty = tid >> 4;

    float acc[4][4];
#pragma unroll
    for (int i = 0; i < 4; i++)
#pragma unroll
        for (int j = 0; j < 4; j++) acc[i][j] = 0.f;

    const int am = tid >> 2;              // 0..63
    const int ak = (tid & 3) * 4;         // 0,4,8,12
    const int bkk = tid >> 4;             // 0..15
    const int bnn = (tid & 15) * 4;       // 0..60

    for (int k0 = 0; k0 < K; k0 += 16) {
        // A tile 64x16
        {
            const int gm = bm + am;
            float4 v = make_float4(0.f, 0.f, 0.f, 0.f);
            if (gm < M)
                v = *reinterpret_cast<const float4*>(A + (size_t)gm * K + k0 + ak);
            As[ak + 0][am] = v.x;
            As[ak + 1][am] = v.y;
            As[ak + 2][am] = v.z;
            As[ak + 3][am] = v.w;
        }
        // B tile 16x64
        {
            const int gn = bn + bnn;
            float4 v;
            if (gn + 3 < N) {
                v = *reinterpret_cast<const float4*>(Bm + (size_t)(k0 + bkk) * N + gn);
            } else {
                float t0 = (gn + 0 < N) ? Bm[(size_t)(k0 + bkk) * N + gn + 0] : 0.f;
                float t1 = (gn + 1 < N) ? Bm[(size_t)(k0 + bkk) * N + gn + 1] : 0.f;
                float t2 = (gn + 2 < N) ? Bm[(size_t)(k0 + bkk) * N + gn + 2] : 0.f;
                float t3 = (gn + 3 < N) ? Bm[(size_t)(k0 + bkk) * N + gn + 3] : 0.f;
                v = make_float4(t0, t1, t2, t3);
            }
            *reinterpret_cast<float4*>(&Bs[bkk][bnn]) = v;
        }
        __syncthreads();
#pragma unroll
        for (int kk = 0; kk < 16; kk++) {
            float a[4], b[4];
#pragma unroll
            for (int i = 0; i < 4; i++) a[i] = As[kk][ty * 4 + i];
#pragma unroll
            for (int j = 0; j < 4; j++) b[j] = Bs[kk][tx * 4 + j];
#pragma unroll
            for (int i = 0; i < 4; i++)
#pragma unroll
                for (int j = 0; j < 4; j++) acc[i][j] = fmaf(a[i], b[j], acc[i][j]);
        }
        __syncthreads();
    }

#pragma unroll
    for (int i = 0; i < 4; i++) {
        const int gm = bm + ty * 4 + i;
        if (gm >= M) continue;
#pragma unroll
        for (int j = 0; j < 4; j++) {
            const int gn = bn + tx * 4 + j;
            if (gn >= N) continue;
            float v = acc[i][j] + bias[gn];
            if (ACCUM) v += C[(size_t)gm * ldc + gn];
            if (ACT == 1) v = sigmf(v);
            C[(size_t)gm * ldc + gn] = v;
        }
    }
}

// ---------------- big 128x128 tiled SGEMM (8x8 micro), no guards ----------
// Requires M%128==0, N%128==0, K%8==0. Used for enc_proj.
__global__ void gemm128_k(const float* __restrict__ A, const float* __restrict__ Bm,
                          const float* __restrict__ bias, float* __restrict__ C,
                          int M, int N, int K)
{
    __shared__ float As[8][128];
    __shared__ float Bs[8][128];
    const int bm = blockIdx.y * 128;
    const int bn = blockIdx.x * 128;
    const int tid = threadIdx.x;      // 0..255
    const int tx = tid & 15;
    const int ty = tid >> 4;

    float acc[8][8];
#pragma unroll
    for (int i = 0; i < 8; i++)
#pragma unroll
        for (int j = 0; j < 8; j++) acc[i][j] = 0.f;

    const int am = tid >> 1;          // 0..127
    const int ak = (tid & 1) * 4;     // 0 or 4
    const int bkk = tid >> 5;         // 0..7
    const int bn4 = (tid & 31) * 4;   // 0..124

    const float* Aptr = A + (size_t)(bm + am) * K + ak;
    const float* Bptr = Bm + (size_t)bkk * N + bn + bn4;

    for (int k0 = 0; k0 < K; k0 += 8) {
        float4 va = *reinterpret_cast<const float4*>(Aptr + k0);
        As[ak + 0][am] = va.x;
        As[ak + 1][am] = va.y;
        As[ak + 2][am] = va.z;
        As[ak + 3][am] = va.w;
        float4 vb = *reinterpret_cast<const float4*>(Bptr + (size_t)k0 * N);
        *reinterpret_cast<float4*>(&Bs[bkk][bn4]) = vb;
        __syncthreads();
#pragma unroll
        for (int kk = 0; kk < 8; kk++) {
            float a[8], b[8];
#pragma unroll
            for (int i = 0; i < 4; i++) {
                a[i]     = As[kk][ty * 4 + i];
                a[i + 4] = As[kk][64 + ty * 4 + i];
                b[i]     = Bs[kk][tx * 4 + i];
                b[i + 4] = Bs[kk][64 + tx * 4 + i];
            }
#pragma unroll
            for (int i = 0; i < 8; i++)
#pragma unroll
                for (int j = 0; j < 8; j++) acc[i][j] = fmaf(a[i], b[j], acc[i][j]);
        }
        __syncthreads();
    }

#pragma unroll
    for (int i = 0; i < 8; i++) {
        const int gm = bm + ((i < 4) ? (ty * 4 + i) : (64 + ty * 4 + i - 4));
#pragma unroll
        for (int j = 0; j < 8; j++) {
            const int gn = bn + ((j < 4) ? (tx * 4 + j) : (64 + tx * 4 + j - 4));
            C[(size_t)gm * N + gn] = acc[i][j] + bias[gn];
        }
    }
}

// ---------------- mean over P -------------------------------------------
__global__ void mean_k(const float* __restrict__ enc, float* __restrict__ out)
{
    const int blocksPerB = ENC / 256;                   // 8
    const int b = blockIdx.x / blocksPerB;
    const int e = (blockIdx.x % blocksPerB) * 256 + threadIdx.x;
    const float* base = enc + (size_t)b * PP * ENC + e;
    float s = 0.f;
#pragma unroll 4
    for (int p = 0; p < PP; p++) s += base[(size_t)p * ENC];
    out[b * ENC + e] = s * (1.f / (float)PP);
}

// ---------------- attention scores --------------------------------------
__global__ void scores_k(const float* __restrict__ encproj, const float* __restrict__ dproj,
                         const float* __restrict__ w_att, const float* __restrict__ b_att,
                         float* __restrict__ scores)
{
    const int bp = blockIdx.x;              // 0..B*P-1
    const int b = bp / PP;
    const float* ep = encproj + (size_t)bp * ATT;
    const float* dp = dproj + (size_t)b * ATT;
    float s = 0.f;
    for (int a = threadIdx.x; a < ATT; a += 128) {
        float e = ep[a] + dp[a];
        s += w_att[a] * fmaxf(e, 0.f);
    }
#pragma unroll
    for (int o = 16; o > 0; o >>= 1) s += __shfl_down_sync(0xffffffffu, s, o);
    __shared__ float ws[4];
    if ((threadIdx.x & 31) == 0) ws[threadIdx.x >> 5] = s;
    __syncthreads();
    if (threadIdx.x == 0) scores[bp] = ws[0] + ws[1] + ws[2] + ws[3] + b_att[0];
}

// ---------------- softmax over P ----------------------------------------
__global__ void softmax_k(const float* __restrict__ scores, float* __restrict__ alpha)
{
    const int b = blockIdx.x;
    const int t = threadIdx.x;              // 256
    __shared__ float red[256];
    float v = (t < PP) ? scores[b * PP + t] : -1e30f;
    red[t] = v;
    __syncthreads();
    for (int s = 128; s > 0; s >>= 1) {
        if (t < s) red[t] = fmaxf(red[t], red[t + s]);
        __syncthreads();
    }
    const float mx = red[0];
    __syncthreads();
    float e = (t < PP) ? expf(v - mx) : 0.f;
    red[t] = e;
    __syncthreads();
    for (int s = 128; s > 0; s >>= 1) {
        if (t < s) red[t] += red[t + s];
        __syncthreads();
    }
    const float sum = red[0];
    if (t < PP) alpha[b * PP + t] = e / sum;
}

// ---------------- context = alpha @ enc_out ------------------------------
__global__ void context_k(const float* __restrict__ alpha, const float* __restrict__ enc,
                          float* __restrict__ ctx)
{
    const int blocksPerB = ENC / 256;       // 8
    const int b = blockIdx.x / blocksPerB;
    const int e = (blockIdx.x % blocksPerB) * 256 + threadIdx.x;
    __shared__ float al[PP];
    for (int p = threadIdx.x; p < PP; p += 256) al[p] = alpha[b * PP + p];
    __syncthreads();
    const float* base = enc + (size_t)b * PP * ENC + e;
    float s = 0.f;
#pragma unroll 4
    for (int p = 0; p < PP; p++) s += al[p] * base[(size_t)p * ENC];
    ctx[b * ENC + e] = s;
}

// ---------------- build x = [emb_t, gate*context] ------------------------
__global__ void buildx_k(const int* __restrict__ captions, const float* __restrict__ emb,
                         const float* __restrict__ gate, const float* __restrict__ ctx,
                         float* __restrict__ x, int t)
{
    const int idx = blockIdx.x * 256 + threadIdx.x;
    if (idx >= BB * (EMB + ENC)) return;
    const int b = idx / (EMB + ENC);
    const int j = idx - b * (EMB + ENC);
    if (j < EMB) {
        const int cap = captions[b * TT + t];
        x[idx] = emb[(size_t)cap * EMB + j];
    } else {
        const int e = j - EMB;
        x[idx] = gate[b * ENC + e] * ctx[b * ENC + e];
    }
}

// ---------------- LSTM cell update ---------------------------------------
__global__ void lstm_k(const float* __restrict__ gates, float* __restrict__ h,
                       float* __restrict__ c)
{
    const int idx = blockIdx.x * 256 + threadIdx.x;
    if (idx >= BB * DEC) return;
    const int b = idx / DEC;
    const int j = idx - b * DEC;
    const float* g = gates + (size_t)b * 4 * DEC;
    const float gi = g[j];
    const float gf = g[DEC + j];
    const float gg = g[2 * DEC + j];
    const float go = g[3 * DEC + j];
    const float cn = sigmf(gf) * c[idx] + sigmf(gi) * tanhf(gg);
    const float hn = sigmf(go) * tanhf(cn);
    c[idx] = cn;
    h[idx] = hn;
}

// =========================================================================
extern "C" void kernel_launch(void* const* d_in, const int* in_sizes, int n_in,
                              void* d_out, int out_size)
{
    const float* enc_out  = (const float*)d_in[0];
    const int*   captions = (const int*)d_in[1];
    const float* emb      = (const float*)d_in[2];
    const float* W_init_h = (const float*)d_in[3];
    const float* b_init_h = (const float*)d_in[4];
    const float* W_init_c = (const float*)d_in[5];
    const float* b_init_c = (const float*)d_in[6];
    const float* W_enc_att = (const float*)d_in[7];
    const float* b_enc_att = (const float*)d_in[8];
    const float* W_dec_att = (const float*)d_in[9];
    const float* b_dec_att = (const float*)d_in[10];
    const float* w_att    = (const float*)d_in[11];
    const float* b_att    = (const float*)d_in[12];
    const float* W_fbeta  = (const float*)d_in[13];
    const float* b_fbeta  = (const float*)d_in[14];
    const float* W_ih     = (const float*)d_in[15];
    const float* b_ih     = (const float*)d_in[16];
    const float* W_hh     = (const float*)d_in[17];
    const float* b_hh     = (const float*)d_in[18];
    const float* W_fc     = (const float*)d_in[19];
    const float* b_fc     = (const float*)d_in[20];
    float* out = (float*)d_out;

    float *p_mean, *p_h, *p_c, *p_encproj, *p_dproj, *p_scores, *p_alpha,
          *p_context, *p_gate, *p_x, *p_gates;
    cudaGetSymbolAddress((void**)&p_mean, g_mean);
    cudaGetSymbolAddress((void**)&p_h, g_h);
    cudaGetSymbolAddress((void**)&p_c, g_c);
    cudaGetSymbolAddress((void**)&p_encproj, g_encproj);
    cudaGetSymbolAddress((void**)&p_dproj, g_dproj);
    cudaGetSymbolAddress((void**)&p_scores, g_scores);
    cudaGetSymbolAddress((void**)&p_alpha, g_alpha);
    cudaGetSymbolAddress((void**)&p_context, g_context);
    cudaGetSymbolAddress((void**)&p_gate, g_gate);
    cudaGetSymbolAddress((void**)&p_x, g_x);
    cudaGetSymbolAddress((void**)&p_gates, g_gates);

    // ---- precompute ----
    mean_k<<<BB * (ENC / 256), 256>>>(enc_out, p_mean);

    // h0 = mean @ W_init_h + b ; c0 = mean @ W_init_c + b
    {
        dim3 g((DEC + 63) / 64, (BB + 63) / 64);
        gemm64_k<0, 0><<<g, 256>>>(p_mean, W_init_h, b_init_h, p_h, BB, DEC, ENC, DEC);
        gemm64_k<0, 0><<<g, 256>>>(p_mean, W_init_c, b_init_c, p_c, BB, DEC, ENC, DEC);
    }

    // enc_proj = enc_out @ W_enc_att + b   [25088, 512], K=2048
    {
        dim3 g(ATT / 128, (BB * PP) / 128);
        gemm128_k<<<g, 256>>>(enc_out, W_enc_att, b_enc_att, p_encproj, BB * PP, ATT, ENC);
    }

    // ---- timestep loop ----
    for (int t = 0; t < TS; t++) {
        // dproj = h @ W_dec_att + b
        {
            dim3 g((ATT + 63) / 64, (BB + 63) / 64);
            gemm64_k<0, 0><<<g, 256>>>(p_h, W_dec_att, b_dec_att, p_dproj, BB, ATT, DEC, ATT);
        }
        // scores, softmax, context
        scores_k<<<BB * PP, 128>>>(p_encproj, p_dproj, w_att, b_att, p_scores);
        softmax_k<<<BB, 256>>>(p_scores, p_alpha);
        context_k<<<BB * (ENC / 256), 256>>>(p_alpha, enc_out, p_context);
        // gate = sigmoid(h @ W_fbeta + b)
        {
            dim3 g((ENC + 63) / 64, (BB + 63) / 64);
            gemm64_k<1, 0><<<g, 256>>>(p_h, W_fbeta, b_fbeta, p_gate, BB, ENC, DEC, ENC);
        }
        // x = [emb_t, gate*context]
        buildx_k<<<(BB * (EMB + ENC) + 255) / 256, 256>>>(captions, emb, p_gate, p_context, p_x, t);
        // gates = x @ W_ih + b_ih ; gates += h @ W_hh + b_hh
        {
            dim3 g((4 * DEC + 63) / 64, (BB + 63) / 64);
            gemm64_k<0, 0><<<g, 256>>>(p_x, W_ih, b_ih, p_gates, BB, 4 * DEC, EMB + ENC, 4 * DEC);
            gemm64_k<0, 1><<<g, 256>>>(p_h, W_hh, b_hh, p_gates, BB, 4 * DEC, DEC, 4 * DEC);
        }
        // LSTM update (writes new h, c)
        lstm_k<<<(BB * DEC + 255) / 256, 256>>>(p_gates, p_h, p_c);
        // out_t = h_new @ W_fc + b_fc  -> d_out[:, t, :]
        {
            dim3 g((VV + 63) / 64, (BB + 63) / 64);
            gemm64_k<0, 0><<<g, 256>>>(p_h, W_fc, b_fc, out + (size_t)t * VV,
                                       BB, VV, DEC, TS * VV);
        }
    }
}

// round 5
// speedup vs baseline: 2.0918x; 2.0918x over previous
#include <cuda_runtime.h>
#include <cuda_fp16.h>
#include <math.h>

#define BB   128
#define PP   196
#define ENC  2048
#define EMB  512
#define DEC  512
#define ATT  512
#define VV   10000
#define TT   20
#define TS   19      // T-1
#define HP   4608    // packed h-proj width: 512 (dec_att) + 2048 (fbeta) + 2048 (hh)
#define OFF_FBETA 512
#define OFF_HH    2560

// ---------------- scratch (device globals, no allocation) ----------------
__device__ float  g_mean[BB * ENC];
__device__ float  g_h[BB * DEC];
__device__ float  g_c[BB * DEC];
__device__ __half g_enc_h[(size_t)BB * PP * ENC];        // fp16 enc_out (102.8 MB)
__device__ __half g_encproj_h[(size_t)BB * PP * ATT];    // fp16 enc_proj (25.7 MB)
__device__ float  g_hproj[BB * HP];                      // [dproj|fbeta|hh]
__device__ float  g_scores[BB * PP];
__device__ float  g_alpha[BB * PP];
__device__ float  g_context[BB * ENC];
__device__ float  g_xc[BB * ENC];                        // gate * context
__device__ float  g_part[4 * BB * 4 * DEC];              // split-K partials
__device__ float  g_Wpack[DEC * HP];
__device__ float  g_bpack[HP];
__device__ float  g_embs[BB * TS * EMB];                 // gathered embeddings
__device__ float  g_embproj[(size_t)BB * TS * 4 * DEC];  // emb @ W_ih_top + b_ih
__device__ float  g_hall[(size_t)BB * TS * DEC];         // all h_t, row = t*128+b

__device__ __forceinline__ float sigmf(float x) { return 1.f / (1.f + expf(-x)); }

// ---------------- generic 64x64 tiled SGEMM (4x4 micro), guarded ----------
// C = act( A[M,K] @ B[K,N] + bias[N] (+C) ). K % 16 == 0, rows 16B-aligned.
// OMAP==1: row r maps to out offset ((r&127)*TS + (r>>7))*ldc  (final W_fc GEMM)
template <int ACT, int ACCUM, int OMAP>
__global__ void gemm64_k(const float* __restrict__ A, const float* __restrict__ Bm,
                         const float* __restrict__ bias, float* __restrict__ C,
                         int M, int N, int K, int ldc)
{
    __shared__ float As[16][64];
    __shared__ float Bs[16][64];
    const int bm = blockIdx.y * 64;
    const int bn = blockIdx.x * 64;
    const int tid = threadIdx.x;
    const int tx = tid & 15;
    const int ty = tid >> 4;

    float acc[4][4];
#pragma unroll
    for (int i = 0; i < 4; i++)
#pragma unroll
        for (int j = 0; j < 4; j++) acc[i][j] = 0.f;

    const int am = tid >> 2;
    const int ak = (tid & 3) * 4;
    const int bkk = tid >> 4;
    const int bnn = (tid & 15) * 4;

    for (int k0 = 0; k0 < K; k0 += 16) {
        {
            const int gm = bm + am;
            float4 v = make_float4(0.f, 0.f, 0.f, 0.f);
            if (gm < M)
                v = *reinterpret_cast<const float4*>(A + (size_t)gm * K + k0 + ak);
            As[ak + 0][am] = v.x;
            As[ak + 1][am] = v.y;
            As[ak + 2][am] = v.z;
            As[ak + 3][am] = v.w;
        }
        {
            const int gn = bn + bnn;
            float4 v;
            if (gn + 3 < N) {
                v = *reinterpret_cast<const float4*>(Bm + (size_t)(k0 + bkk) * N + gn);
            } else {
                float t0 = (gn + 0 < N) ? Bm[(size_t)(k0 + bkk) * N + gn + 0] : 0.f;
                float t1 = (gn + 1 < N) ? Bm[(size_t)(k0 + bkk) * N + gn + 1] : 0.f;
                float t2 = (gn + 2 < N) ? Bm[(size_t)(k0 + bkk) * N + gn + 2] : 0.f;
                float t3 = (gn + 3 < N) ? Bm[(size_t)(k0 + bkk) * N + gn + 3] : 0.f;
                v = make_float4(t0, t1, t2, t3);
            }
            *reinterpret_cast<float4*>(&Bs[bkk][bnn]) = v;
        }
        __syncthreads();
#pragma unroll
        for (int kk = 0; kk < 16; kk++) {
            float a[4], b[4];
#pragma unroll
            for (int i = 0; i < 4; i++) a[i] = As[kk][ty * 4 + i];
#pragma unroll
            for (int j = 0; j < 4; j++) b[j] = Bs[kk][tx * 4 + j];
#pragma unroll
            for (int i = 0; i < 4; i++)
#pragma unroll
                for (int j = 0; j < 4; j++) acc[i][j] = fmaf(a[i], b[j], acc[i][j]);
        }
        __syncthreads();
    }

#pragma unroll
    for (int i = 0; i < 4; i++) {
        const int gm = bm + ty * 4 + i;
        if (gm >= M) continue;
        size_t rowoff;
        if (OMAP == 1) rowoff = (size_t)((gm & 127) * TS + (gm >> 7)) * ldc;
        else           rowoff = (size_t)gm * ldc;
#pragma unroll
        for (int j = 0; j < 4; j++) {
            const int gn = bn + tx * 4 + j;
            if (gn >= N) continue;
            float v = acc[i][j] + bias[gn];
            if (ACCUM) v += C[rowoff + gn];
            if (ACT == 1) v = sigmf(v);
            C[rowoff + gn] = v;
        }
    }
}

// ---------------- split-K partial GEMM: C_part[z] = A[:,zK..] @ B[zK..,:] --
// M=128, N=2048, Kc=512 per z-slab. No bias, plain store into slab z.
__global__ void gemm64_kz(const float* __restrict__ A, const float* __restrict__ Bm,
                          float* __restrict__ Cpart)
{
    const int KALL = ENC;        // A row stride
    const int N = 4 * DEC;       // B row stride / C cols
    const int KC = 512;
    __shared__ float As[16][64];
    __shared__ float Bs[16][64];
    const int bm = blockIdx.y * 64;
    const int bn = blockIdx.x * 64;
    const int z  = blockIdx.z;
    const int kbase = z * KC;
    const int tid = threadIdx.x;
    const int tx = tid & 15;
    const int ty = tid >> 4;

    float acc[4][4];
#pragma unroll
    for (int i = 0; i < 4; i++)
#pragma unroll
        for (int j = 0; j < 4; j++) acc[i][j] = 0.f;

    const int am = tid >> 2;
    const int ak = (tid & 3) * 4;
    const int bkk = tid >> 4;
    const int bnn = (tid & 15) * 4;

    for (int k0 = 0; k0 < KC; k0 += 16) {
        {
            const int gm = bm + am;
            float4 v = make_float4(0.f, 0.f, 0.f, 0.f);
            if (gm < BB)
                v = *reinterpret_cast<const float4*>(A + (size_t)gm * KALL + kbase + k0 + ak);
            As[ak + 0][am] = v.x;
            As[ak + 1][am] = v.y;
            As[ak + 2][am] = v.z;
            As[ak + 3][am] = v.w;
        }
        {
            float4 v = *reinterpret_cast<const float4*>(
                Bm + (size_t)(kbase + k0 + bkk) * N + bn + bnn);
            *reinterpret_cast<float4*>(&Bs[bkk][bnn]) = v;
        }
        __syncthreads();
#pragma unroll
        for (int kk = 0; kk < 16; kk++) {
            float a[4], b[4];
#pragma unroll
            for (int i = 0; i < 4; i++) a[i] = As[kk][ty * 4 + i];
#pragma unroll
            for (int j = 0; j < 4; j++) b[j] = Bs[kk][tx * 4 + j];
#pragma unroll
            for (int i = 0; i < 4; i++)
#pragma unroll
                for (int j = 0; j < 4; j++) acc[i][j] = fmaf(a[i], b[j], acc[i][j]);
        }
        __syncthreads();
    }

    float* Cz = Cpart + (size_t)z * BB * N;
#pragma unroll
    for (int i = 0; i < 4; i++) {
        const int gm = bm + ty * 4 + i;
        if (gm >= BB) continue;
#pragma unroll
        for (int j = 0; j < 4; j++) {
            const int gn = bn + tx * 4 + j;
            Cz[(size_t)gm * N + gn] = acc[i][j];
        }
    }
}

// ---------------- big 128x128 tiled SGEMM (8x8 micro), no guards ----------
// M%128==0, N%128==0, K%8==0. OutT = float or __half.
template <typename OutT>
__global__ void gemm128_k(const float* __restrict__ A, const float* __restrict__ Bm,
                          const float* __restrict__ bias, OutT* __restrict__ C,
                          int M, int N, int K)
{
    __shared__ float As[8][128];
    __shared__ float Bs[8][128];
    const int bm = blockIdx.y * 128;
    const int bn = blockIdx.x * 128;
    const int tid = threadIdx.x;
    const int tx = tid & 15;
    const int ty = tid >> 4;

    float acc[8][8];
#pragma unroll
    for (int i = 0; i < 8; i++)
#pragma unroll
        for (int j = 0; j < 8; j++) acc[i][j] = 0.f;

    const int am = tid >> 1;
    const int ak = (tid & 1) * 4;
    const int bkk = tid >> 5;
    const int bn4 = (tid & 31) * 4;

    const float* Aptr = A + (size_t)(bm + am) * K + ak;
    const float* Bptr = Bm + (size_t)bkk * N + bn + bn4;

    for (int k0 = 0; k0 < K; k0 += 8) {
        float4 va = *reinterpret_cast<const float4*>(Aptr + k0);
        As[ak + 0][am] = va.x;
        As[ak + 1][am] = va.y;
        As[ak + 2][am] = va.z;
        As[ak + 3][am] = va.w;
        float4 vb = *reinterpret_cast<const float4*>(Bptr + (size_t)k0 * N);
        *reinterpret_cast<float4*>(&Bs[bkk][bn4]) = vb;
        __syncthreads();
#pragma unroll
        for (int kk = 0; kk < 8; kk++) {
            float a[8], b[8];
#pragma unroll
            for (int i = 0; i < 4; i++) {
                a[i]     = As[kk][ty * 4 + i];
                a[i + 4] = As[kk][64 + ty * 4 + i];
                b[i]     = Bs[kk][tx * 4 + i];
                b[i + 4] = Bs[kk][64 + tx * 4 + i];
            }
#pragma unroll
            for (int i = 0; i < 8; i++)
#pragma unroll
                for (int j = 0; j < 8; j++) acc[i][j] = fmaf(a[i], b[j], acc[i][j]);
        }
        __syncthreads();
    }

#pragma unroll
    for (int i = 0; i < 8; i++) {
        const int gm = bm + ((i < 4) ? (ty * 4 + i) : (64 + ty * 4 + i - 4));
#pragma unroll
        for (int j = 0; j < 8; j++) {
            const int gn = bn + ((j < 4) ? (tx * 4 + j) : (64 + tx * 4 + j - 4));
            float v = acc[i][j] + bias[gn];
            C[(size_t)gm * N + gn] = (OutT)v;
        }
    }
}

// ---------------- mean over P -------------------------------------------
__global__ void mean_k(const float* __restrict__ enc, float* __restrict__ out)
{
    const int blocksPerB = ENC / 256;
    const int b = blockIdx.x / blocksPerB;
    const int e = (blockIdx.x % blocksPerB) * 256 + threadIdx.x;
    const float* base = enc + (size_t)b * PP * ENC + e;
    float s = 0.f;
#pragma unroll 4
    for (int p = 0; p < PP; p++) s += base[(size_t)p * ENC];
    out[b * ENC + e] = s * (1.f / (float)PP);
}

// ---------------- fp32 -> fp16 convert -----------------------------------
__global__ void tohalf_k(const float* __restrict__ in, __half* __restrict__ out, size_t n2)
{
    const size_t i = (size_t)blockIdx.x * 256 + threadIdx.x;
    if (i >= n2) return;
    float2 v = reinterpret_cast<const float2*>(in)[i];
    reinterpret_cast<__half2*>(out)[i] = __floats2half2_rn(v.x, v.y);
}

// ---------------- weight packing [W_dec_att | W_fbeta | W_hh] ------------
__global__ void pack_k(const float* __restrict__ Wda, const float* __restrict__ Wfb,
                       const float* __restrict__ Whh, float* __restrict__ Wp)
{
    const int idx = blockIdx.x * 256 + threadIdx.x;
    if (idx >= DEC * HP) return;
    const int r = idx / HP;
    const int c = idx - r * HP;
    float v;
    if (c < OFF_FBETA)      v = Wda[r * ATT + c];
    else if (c < OFF_HH)    v = Wfb[r * ENC + (c - OFF_FBETA)];
    else                    v = Whh[r * (4 * DEC) + (c - OFF_HH)];
    Wp[idx] = v;
}
__global__ void packb_k(const float* __restrict__ bda, const float* __restrict__ bfb,
                        const float* __restrict__ bhh, float* __restrict__ bp)
{
    const int c = blockIdx.x * 256 + threadIdx.x;
    if (c >= HP) return;
    float v;
    if (c < OFF_FBETA)      v = bda[c];
    else if (c < OFF_HH)    v = bfb[c - OFF_FBETA];
    else                    v = bhh[c - OFF_HH];
    bp[c] = v;
}

// ---------------- gather embeddings for all timesteps --------------------
__global__ void gather_k(const int* __restrict__ captions, const float* __restrict__ emb,
                         float* __restrict__ out)
{
    const int idx = blockIdx.x * 256 + threadIdx.x;   // over BB*TS*EMB
    if (idx >= BB * TS * EMB) return;
    const int j = idx & (EMB - 1);
    const int row = idx >> 9;          // t*128 + b
    const int b = row & 127;
    const int t = row >> 7;
    const int cap = captions[b * TT + t];
    out[idx] = emb[(size_t)cap * EMB + j];
}

// ---------------- attention scores (fp16 encproj) ------------------------
__global__ void scores_k(const __half* __restrict__ encproj, const float* __restrict__ hproj,
                         const float* __restrict__ w_att, const float* __restrict__ b_att,
                         float* __restrict__ scores)
{
    const int bp = blockIdx.x;
    const int b = bp / PP;
    const __half* ep = encproj + (size_t)bp * ATT;
    const float* dp = hproj + (size_t)b * HP;          // dproj at offset 0
    const int a0 = threadIdx.x * 4;                    // 128 threads x 4
    float s = 0.f;
    __half2 e01 = *reinterpret_cast<const __half2*>(ep + a0);
    __half2 e23 = *reinterpret_cast<const __half2*>(ep + a0 + 2);
    float4 d = *reinterpret_cast<const float4*>(dp + a0);
    float4 w = *reinterpret_cast<const float4*>(w_att + a0);
    s += w.x * fmaxf(__low2float(e01)  + d.x, 0.f);
    s += w.y * fmaxf(__high2float(e01) + d.y, 0.f);
    s += w.z * fmaxf(__low2float(e23)  + d.z, 0.f);
    s += w.w * fmaxf(__high2float(e23) + d.w, 0.f);
#pragma unroll
    for (int o = 16; o > 0; o >>= 1) s += __shfl_down_sync(0xffffffffu, s, o);
    __shared__ float ws[4];
    if ((threadIdx.x & 31) == 0) ws[threadIdx.x >> 5] = s;
    __syncthreads();
    if (threadIdx.x == 0) scores[bp] = ws[0] + ws[1] + ws[2] + ws[3] + b_att[0];
}

// ---------------- softmax over P ----------------------------------------
__global__ void softmax_k(const float* __restrict__ scores, float* __restrict__ alpha)
{
    const int b = blockIdx.x;
    const int t = threadIdx.x;
    __shared__ float red[256];
    float v = (t < PP) ? scores[b * PP + t] : -1e30f;
    red[t] = v;
    __syncthreads();
    for (int s = 128; s > 0; s >>= 1) {
        if (t < s) red[t] = fmaxf(red[t], red[t + s]);
        __syncthreads();
    }
    const float mx = red[0];
    __syncthreads();
    float e = (t < PP) ? expf(v - mx) : 0.f;
    red[t] = e;
    __syncthreads();
    for (int s = 128; s > 0; s >>= 1) {
        if (t < s) red[t] += red[t + s];
        __syncthreads();
    }
    const float sum = red[0];
    if (t < PP) alpha[b * PP + t] = e / sum;
}

// ---------------- context = alpha @ enc_out (fp16 enc) -------------------
__global__ void contexth_k(const float* __restrict__ alpha, const __half* __restrict__ enc,
                           float* __restrict__ ctx)
{
    const int blocksPerB = ENC / 512;                  // 4 (256 thr x 2 elem)
    const int b = blockIdx.x / blocksPerB;
    const int e = ((blockIdx.x % blocksPerB) * 256 + threadIdx.x) * 2;
    __shared__ float al[PP];
    for (int p = threadIdx.x; p < PP; p += 256) al[p] = alpha[b * PP + p];
    __syncthreads();
    const __half* base = enc + (size_t)b * PP * ENC + e;
    float s0 = 0.f, s1 = 0.f;
#pragma unroll 4
    for (int p = 0; p < PP; p++) {
        __half2 v = *reinterpret_cast<const __half2*>(base + (size_t)p * ENC);
        s0 = fmaf(al[p], __low2float(v), s0);
        s1 = fmaf(al[p], __high2float(v), s1);
    }
    ctx[b * ENC + e]     = s0;
    ctx[b * ENC + e + 1] = s1;
}

// ---------------- xc = sigmoid(fbeta) * context --------------------------
__global__ void gatex_k(const float* __restrict__ hproj, const float* __restrict__ ctx,
                        float* __restrict__ xc)
{
    const int idx = blockIdx.x * 256 + threadIdx.x;
    if (idx >= BB * ENC) return;
    const int b = idx >> 11;
    const int e = idx & (ENC - 1);
    const float g = sigmf(hproj[(size_t)b * HP + OFF_FBETA + e]);
    xc[idx] = g * ctx[idx];
}

// ---------------- fused LSTM: sum gate sources + cell update -------------
__global__ void lstm2_k(const float* __restrict__ embproj, const float* __restrict__ hproj,
                        const float* __restrict__ part, float* __restrict__ h,
                        float* __restrict__ c, float* __restrict__ hall, int t)
{
    const int idx = blockIdx.x * 256 + threadIdx.x;    // over BB*DEC
    if (idx >= BB * DEC) return;
    const int b = idx >> 9;
    const int j = idx & (DEC - 1);
    const float* ep = embproj + (size_t)(t * BB + b) * (4 * DEC);
    const float* hp = hproj + (size_t)b * HP + OFF_HH;
    const float* p0 = part + (size_t)b * (4 * DEC);
    const float* p1 = p0 + (size_t)BB * 4 * DEC;
    const float* p2 = p1 + (size_t)BB * 4 * DEC;
    const float* p3 = p2 + (size_t)BB * 4 * DEC;

    float gt[4];
#pragma unroll
    for (int q = 0; q < 4; q++) {
        const int col = j + q * DEC;
        gt[q] = ep[col] + hp[col] + p0[col] + p1[col] + p2[col] + p3[col];
    }
    const float cn = sigmf(gt[1]) * c[idx] + sigmf(gt[0]) * tanhf(gt[2]);
    const float hn = sigmf(gt[3]) * tanhf(cn);
    c[idx] = cn;
    h[idx] = hn;
    hall[(size_t)(t * BB + b) * DEC + j] = hn;
}

// =========================================================================
extern "C" void kernel_launch(void* const* d_in, const int* in_sizes, int n_in,
                              void* d_out, int out_size)
{
    const float* enc_out  = (const float*)d_in[0];
    const int*   captions = (const int*)d_in[1];
    const float* emb      = (const float*)d_in[2];
    const float* W_init_h = (const float*)d_in[3];
    const float* b_init_h = (const float*)d_in[4];
    const float* W_init_c = (const float*)d_in[5];
    const float* b_init_c = (const float*)d_in[6];
    const float* W_enc_att = (const float*)d_in[7];
    const float* b_enc_att = (const float*)d_in[8];
    const float* W_dec_att = (const float*)d_in[9];
    const float* b_dec_att = (const float*)d_in[10];
    const float* w_att    = (const float*)d_in[11];
    const float* b_att    = (const float*)d_in[12];
    const float* W_fbeta  = (const float*)d_in[13];
    const float* b_fbeta  = (const float*)d_in[14];
    const float* W_ih     = (const float*)d_in[15];
    const float* b_ih     = (const float*)d_in[16];
    const float* W_hh     = (const float*)d_in[17];
    const float* b_hh     = (const float*)d_in[18];
    const float* W_fc     = (const float*)d_in[19];
    const float* b_fc     = (const float*)d_in[20];
    float* out = (float*)d_out;

    float *p_mean, *p_h, *p_c, *p_hproj, *p_scores, *p_alpha, *p_context,
          *p_xc, *p_part, *p_Wpack, *p_bpack, *p_embs, *p_embproj, *p_hall;
    __half *p_ench, *p_encprojh;
    cudaGetSymbolAddress((void**)&p_mean, g_mean);
    cudaGetSymbolAddress((void**)&p_h, g_h);
    cudaGetSymbolAddress((void**)&p_c, g_c);
    cudaGetSymbolAddress((void**)&p_ench, g_enc_h);
    cudaGetSymbolAddress((void**)&p_encprojh, g_encproj_h);
    cudaGetSymbolAddress((void**)&p_hproj, g_hproj);
    cudaGetSymbolAddress((void**)&p_scores, g_scores);
    cudaGetSymbolAddress((void**)&p_alpha, g_alpha);
    cudaGetSymbolAddress((void**)&p_context, g_context);
    cudaGetSymbolAddress((void**)&p_xc, g_xc);
    cudaGetSymbolAddress((void**)&p_part, g_part);
    cudaGetSymbolAddress((void**)&p_Wpack, g_Wpack);
    cudaGetSymbolAddress((void**)&p_bpack, g_bpack);
    cudaGetSymbolAddress((void**)&p_embs, g_embs);
    cudaGetSymbolAddress((void**)&p_embproj, g_embproj);
    cudaGetSymbolAddress((void**)&p_hall, g_hall);

    const float* W_ih_bot = W_ih + (size_t)EMB * (4 * DEC);

    // ================= precompute (off critical path) =================
    mean_k<<<BB * (ENC / 256), 256>>>(enc_out, p_mean);
    {
        dim3 g((DEC + 63) / 64, (BB + 63) / 64);
        gemm64_k<0, 0, 0><<<g, 256>>>(p_mean, W_init_h, b_init_h, p_h, BB, DEC, ENC, DEC);
        gemm64_k<0, 0, 0><<<g, 256>>>(p_mean, W_init_c, b_init_c, p_c, BB, DEC, ENC, DEC);
    }
    // fp16 copy of enc_out
    {
        size_t n2 = (size_t)BB * PP * ENC / 2;
        tohalf_k<<<(unsigned)((n2 + 255) / 256), 256>>>(enc_out, p_ench, n2);
    }
    // pack h-projection weights
    pack_k<<<(DEC * HP + 255) / 256, 256>>>(W_dec_att, W_fbeta, W_hh, p_Wpack);
    packb_k<<<(HP + 255) / 256, 256>>>(b_dec_att, b_fbeta, b_hh, p_bpack);
    // gather embeddings, project all timesteps: embproj = embs @ W_ih_top + b_ih
    gather_k<<<(BB * TS * EMB + 255) / 256, 256>>>(captions, emb, p_embs);
    {
        dim3 g((4 * DEC) / 128, (BB * TS) / 128);
        gemm128_k<float><<<g, 256>>>(p_embs, W_ih, b_ih, p_embproj, BB * TS, 4 * DEC, EMB);
    }
    // enc_proj (fp16 out) = enc_out @ W_enc_att + b
    {
        dim3 g(ATT / 128, (BB * PP) / 128);
        gemm128_k<__half><<<g, 256>>>(enc_out, W_enc_att, b_enc_att, p_encprojh,
                                      BB * PP, ATT, ENC);
    }

    // ================= recurrent loop (critical path) =================
    for (int t = 0; t < TS; t++) {
        // hproj = h @ [W_dec_att | W_fbeta | W_hh] + bpack   [128, 4608]
        {
            dim3 g(HP / 64, BB / 64);
            gemm64_k<0, 0, 0><<<g, 256>>>(p_h, p_Wpack, p_bpack, p_hproj,
                                          BB, HP, DEC, HP);
        }
        scores_k<<<BB * PP, 128>>>(p_encprojh, p_hproj, w_att, b_att, p_scores);
        softmax_k<<<BB, 256>>>(p_scores, p_alpha);
        contexth_k<<<BB * (ENC / 512), 256>>>(p_alpha, p_ench, p_context);
        gatex_k<<<(BB * ENC + 255) / 256, 256>>>(p_hproj, p_context, p_xc);
        // ctx gate partials: xc @ W_ih_bot, split-K x4
        {
            dim3 g((4 * DEC) / 64, BB / 64, 4);
            gemm64_kz<<<g, 256>>>(p_xc, W_ih_bot, p_part);
        }
        lstm2_k<<<(BB * DEC + 255) / 256, 256>>>(p_embproj, p_hproj, p_part,
                                                 p_h, p_c, p_hall, t);
    }

    // ================= final output GEMM =================
    // out[b][t][:] = hall[t*128+b] @ W_fc + b_fc
    {
        dim3 g((VV + 63) / 64, (BB * TS + 63) / 64);
        gemm64_k<0, 0, 1><<<g, 256>>>(p_hall, W_fc, b_fc, out,
                                      BB * TS, VV, DEC, VV);
    }
}

// round 11
// speedup vs baseline: 2.9325x; 1.4018x over previous
#include <cuda_runtime.h>
#include <cuda_fp16.h>
#include <math.h>
#include <stdint.h>

#define BB   128
#define PP   196
#define ENC  2048
#define EMB  512
#define DEC  512
#define ATT  512
#define VV   10000
#define VPAD 10112   // 79 * 128
#define TT   20
#define TS   19      // T-1
#define HP   4608    // packed h-proj width: 512 (dec_att) + 2048 (fbeta) + 2048 (hh)
#define OFF_FBETA 512
#define OFF_HH    2560

// ---------------- scratch (device globals, no allocation) ----------------
__device__ float  g_mean[BB * ENC];
__device__ float  g_h[BB * DEC];
__device__ float  g_c[BB * DEC];
__device__ __half g_enc_h[(size_t)BB * PP * ENC];        // fp16 enc_out
__device__ __half g_encproj_h[(size_t)BB * PP * ATT];    // fp16 enc_proj
__device__ float  g_hproj[BB * HP];                      // [dproj|fbeta|hh]
__device__ float  g_scores[BB * PP];
__device__ float  g_alpha[BB * PP];
__device__ float  g_context[BB * ENC];
__device__ float  g_xc[BB * ENC];                        // gate * context
__device__ float  g_part[4 * BB * 4 * DEC];              // split-K partials
__device__ float  g_Wpack[DEC * HP];
__device__ float  g_bpack[HP];
__device__ float  g_embs[BB * TS * EMB];                 // gathered embeddings
__device__ float  g_embproj[(size_t)BB * TS * 4 * DEC];  // emb @ W_ih_top + b_ih
__device__ __half g_hall_h[(size_t)BB * TS * DEC];       // all h_t fp16, row = t*128+b
__device__ __half g_wencT[(size_t)ATT * ENC];            // W_enc_att^T fp16 [512,2048]
__device__ __half g_wfcT[(size_t)VPAD * DEC];            // W_fc^T fp16 padded [10112,512]

__device__ __forceinline__ float sigmf(float x) { return 1.f / (1.f + expf(-x)); }

// ---------------- warp MMA m16n8k16 fp16->fp32 ---------------------------
__device__ __forceinline__ void mma16816(float* c, uint32_t a0, uint32_t a1,
                                         uint32_t a2, uint32_t a3,
                                         uint32_t b0, uint32_t b1)
{
    asm volatile(
        "mma.sync.aligned.m16n8k16.row.col.f32.f16.f16.f32 "
        "{%0,%1,%2,%3}, {%4,%5,%6,%7}, {%8,%9}, {%0,%1,%2,%3};"
        : "+f"(c[0]), "+f"(c[1]), "+f"(c[2]), "+f"(c[3])
        : "r"(a0), "r"(a1), "r"(a2), "r"(a3), "r"(b0), "r"(b1));
}

// ================= HMMA fp16 GEMM: D = A @ Bt^T + bias ===================
// A [M,K] fp16 K-major (lda), Bt [Npad,K] fp16 K-major (ldb). Tile 128x128,
// K = NC*64. 256 threads = 8 warps (4 M x 2 N), each warp 32x64 via 2x8
// m16n8k16 fragments.
// OUTMODE 0: fp16 row-major store to Ch (ldc).
// OUTMODE 1: fp32 store with OMAP row ((gm&127)*TS + (gm>>7)), guard gn<VV.
template <int NC, int OUTMODE>
__global__ void __launch_bounds__(256) hgemm_k(
    const __half* __restrict__ A, int lda,
    const __half* __restrict__ Bt, int ldb,
    const float* __restrict__ bias,
    float* __restrict__ Cf, __half* __restrict__ Ch, int ldc)
{
    __shared__ __half As[128 * 64];
    __shared__ __half Bs[128 * 64];
    char* Abuf = (char*)As;
    char* Bbuf = (char*)Bs;

    const int tid = threadIdx.x;
    const int bm = blockIdx.y * 128;
    const int bn = blockIdx.x * 128;
    const int lane = tid & 31, wid = tid >> 5;
    const int wm = wid & 3, wn = wid >> 2;        // 4 x 2 warp grid
    const int g = lane >> 2, tig = lane & 3;

    float acc[2][8][4];
#pragma unroll
    for (int mi = 0; mi < 2; mi++)
#pragma unroll
        for (int ni = 0; ni < 8; ni++)
#pragma unroll
            for (int q = 0; q < 4; q++) acc[mi][ni][q] = 0.f;

    // gmem copy mapping: 1024 uint4 per 16KB tile, 4 per thread
    const int row0 = tid >> 3, slot = tid & 7;    // rows step 32 per i
    const __half* Ab = A + (size_t)(bm + row0) * lda + slot * 8;
    const __half* Bb = Bt + (size_t)(bn + row0) * ldb + slot * 8;

    uint4 ar[4], br[4];
#pragma unroll
    for (int i = 0; i < 4; i++) {
        ar[i] = *(const uint4*)(Ab + (size_t)(i * 32) * lda);
        br[i] = *(const uint4*)(Bb + (size_t)(i * 32) * ldb);
    }

    for (int k = 0; k < NC; k++) {
        if (k) __syncthreads();
#pragma unroll
        for (int i = 0; i < 4; i++) {
            const uint32_t off = (row0 + i * 32) * 128 + slot * 16;
            const uint32_t sw = off ^ ((off >> 3) & 0x70);
            *(uint4*)(Abuf + sw) = ar[i];
            *(uint4*)(Bbuf + sw) = br[i];
        }
        __syncthreads();
        if (k + 1 < NC) {
#pragma unroll
            for (int i = 0; i < 4; i++) {
                ar[i] = *(const uint4*)(Ab + (size_t)(k + 1) * 64 + (size_t)(i * 32) * lda);
                br[i] = *(const uint4*)(Bb + (size_t)(k + 1) * 64 + (size_t)(i * 32) * ldb);
            }
        }
#pragma unroll
        for (int kk = 0; kk < 4; kk++) {
            uint32_t af[2][4];
#pragma unroll
            for (int mi = 0; mi < 2; mi++) {
                const int r0 = wm * 32 + mi * 16 + g;
                const int r1 = r0 + 8;
                const uint32_t c0 = kk * 32 + 4 * tig;
                const uint32_t c1 = c0 + 16;
                af[mi][0] = *(const uint32_t*)(Abuf + r0 * 128 + (c0 ^ ((r0 & 7) << 4)));
                af[mi][1] = *(const uint32_t*)(Abuf + r1 * 128 + (c0 ^ ((r1 & 7) << 4)));
                af[mi][2] = *(const uint32_t*)(Abuf + r0 * 128 + (c1 ^ ((r0 & 7) << 4)));
                af[mi][3] = *(const uint32_t*)(Abuf + r1 * 128 + (c1 ^ ((r1 & 7) << 4)));
            }
#pragma unroll
            for (int ni = 0; ni < 8; ni++) {
                const int n = wn * 64 + ni * 8 + g;
                const uint32_t kb0 = kk * 32 + 4 * tig;
                const uint32_t b0 = *(const uint32_t*)(Bbuf + n * 128 + (kb0 ^ ((n & 7) << 4)));
                const uint32_t b1 = *(const uint32_t*)(Bbuf + n * 128 + ((kb0 + 16) ^ ((n & 7) << 4)));
                mma16816(acc[0][ni], af[0][0], af[0][1], af[0][2], af[0][3], b0, b1);
                mma16816(acc[1][ni], af[1][0], af[1][1], af[1][2], af[1][3], b0, b1);
            }
        }
    }

    // epilogue
#pragma unroll
    for (int mi = 0; mi < 2; mi++) {
        const int gm0 = bm + wm * 32 + mi * 16 + g;
        const int gm1 = gm0 + 8;
#pragma unroll
        for (int ni = 0; ni < 8; ni++) {
            const int gn = bn + wn * 64 + ni * 8 + 2 * tig;
            const float bz0 = bias[gn], bz1 = bias[gn + 1];
            if (OUTMODE == 0) {
                *(__half2*)(Ch + (size_t)gm0 * ldc + gn) =
                    __floats2half2_rn(acc[mi][ni][0] + bz0, acc[mi][ni][1] + bz1);
                *(__half2*)(Ch + (size_t)gm1 * ldc + gn) =
                    __floats2half2_rn(acc[mi][ni][2] + bz0, acc[mi][ni][3] + bz1);
            } else {
                const size_t ro0 = (size_t)((gm0 & 127) * TS + (gm0 >> 7)) * ldc;
                const size_t ro1 = (size_t)((gm1 & 127) * TS + (gm1 >> 7)) * ldc;
                if (gn < VV)     Cf[ro0 + gn]     = acc[mi][ni][0] + bz0;
                if (gn + 1 < VV) Cf[ro0 + gn + 1] = acc[mi][ni][1] + bz1;
                if (gn < VV)     Cf[ro1 + gn]     = acc[mi][ni][2] + bz0;
                if (gn + 1 < VV) Cf[ro1 + gn + 1] = acc[mi][ni][3] + bz1;
            }
        }
    }
}

// ---------------- transpose fp32 [K,N] -> fp16 [Npad,K], zero-padded ------
__global__ void transh_k(const float* __restrict__ src, __half* __restrict__ dst,
                         int K, int N, int Npad)
{
    __shared__ float t[32][33];
    const int n0 = blockIdx.x * 32, k0 = blockIdx.y * 32;
    const int x = threadIdx.x & 31, y = threadIdx.x >> 5;   // 256 thr: y 0..7
#pragma unroll
    for (int dy = 0; dy < 32; dy += 8) {
        const int k = k0 + y + dy, n = n0 + x;
        t[y + dy][x] = (k < K && n < N) ? src[(size_t)k * N + n] : 0.f;
    }
    __syncthreads();
#pragma unroll
    for (int dy = 0; dy < 32; dy += 8) {
        const int n = n0 + y + dy, k = k0 + x;
        if (n < Npad && k < K) dst[(size_t)n * K + k] = __float2half(t[x][y + dy]);
    }
}

// ---------------- generic 64x64 tiled SGEMM (4x4 micro), guarded ----------
template <int ACT, int ACCUM>
__global__ void gemm64_k(const float* __restrict__ A, const float* __restrict__ Bm,
                         const float* __restrict__ bias, float* __restrict__ C,
                         int M, int N, int K, int ldc)
{
    __shared__ float As[16][64];
    __shared__ float Bs[16][64];
    const int bm = blockIdx.y * 64;
    const int bn = blockIdx.x * 64;
    const int tid = threadIdx.x;
    const int tx = tid & 15;
    const int ty = tid >> 4;

    float acc[4][4];
#pragma unroll
    for (int i = 0; i < 4; i++)
#pragma unroll
        for (int j = 0; j < 4; j++) acc[i][j] = 0.f;

    const int am = tid >> 2;
    const int ak = (tid & 3) * 4;
    const int bkk = tid >> 4;
    const int bnn = (tid & 15) * 4;

    for (int k0 = 0; k0 < K; k0 += 16) {
        {
            const int gm = bm + am;
            float4 v = make_float4(0.f, 0.f, 0.f, 0.f);
            if (gm < M)
                v = *reinterpret_cast<const float4*>(A + (size_t)gm * K + k0 + ak);
            As[ak + 0][am] = v.x;
            As[ak + 1][am] = v.y;
            As[ak + 2][am] = v.z;
            As[ak + 3][am] = v.w;
        }
        {
            const int gn = bn + bnn;
            float4 v;
            if (gn + 3 < N) {
                v = *reinterpret_cast<const float4*>(Bm + (size_t)(k0 + bkk) * N + gn);
            } else {
                float t0 = (gn + 0 < N) ? Bm[(size_t)(k0 + bkk) * N + gn + 0] : 0.f;
                float t1 = (gn + 1 < N) ? Bm[(size_t)(k0 + bkk) * N + gn + 1] : 0.f;
                float t2 = (gn + 2 < N) ? Bm[(size_t)(k0 + bkk) * N + gn + 2] : 0.f;
                float t3 = (gn + 3 < N) ? Bm[(size_t)(k0 + bkk) * N + gn + 3] : 0.f;
                v = make_float4(t0, t1, t2, t3);
            }
            *reinterpret_cast<float4*>(&Bs[bkk][bnn]) = v;
        }
        __syncthreads();
#pragma unroll
        for (int kk = 0; kk < 16; kk++) {
            float a[4], b[4];
#pragma unroll
            for (int i = 0; i < 4; i++) a[i] = As[kk][ty * 4 + i];
#pragma unroll
            for (int j = 0; j < 4; j++) b[j] = Bs[kk][tx * 4 + j];
#pragma unroll
            for (int i = 0; i < 4; i++)
#pragma unroll
                for (int j = 0; j < 4; j++) acc[i][j] = fmaf(a[i], b[j], acc[i][j]);
        }
        __syncthreads();
    }

#pragma unroll
    for (int i = 0; i < 4; i++) {
        const int gm = bm + ty * 4 + i;
        if (gm >= M) continue;
        const size_t rowoff = (size_t)gm * ldc;
#pragma unroll
        for (int j = 0; j < 4; j++) {
            const int gn = bn + tx * 4 + j;
            if (gn >= N) continue;
            float v = acc[i][j] + bias[gn];
            if (ACCUM) v += C[rowoff + gn];
            if (ACT == 1) v = sigmf(v);
            C[rowoff + gn] = v;
        }
    }
}

// ---------------- split-K partial GEMM over xc @ W_ih_bot -----------------
__global__ void gemm64_kz(const float* __restrict__ A, const float* __restrict__ Bm,
                          float* __restrict__ Cpart)
{
    const int KALL = ENC;
    const int N = 4 * DEC;
    const int KC = 512;
    __shared__ float As[16][64];
    __shared__ float Bs[16][64];
    const int bm = blockIdx.y * 64;
    const int bn = blockIdx.x * 64;
    const int z  = blockIdx.z;
    const int kbase = z * KC;
    const int tid = threadIdx.x;
    const int tx = tid & 15;
    const int ty = tid >> 4;

    float acc[4][4];
#pragma unroll
    for (int i = 0; i < 4; i++)
#pragma unroll
        for (int j = 0; j < 4; j++) acc[i][j] = 0.f;

    const int am = tid >> 2;
    const int ak = (tid & 3) * 4;
    const int bkk = tid >> 4;
    const int bnn = (tid & 15) * 4;

    for (int k0 = 0; k0 < KC; k0 += 16) {
        {
            const int gm = bm + am;
            float4 v = make_float4(0.f, 0.f, 0.f, 0.f);
            if (gm < BB)
                v = *reinterpret_cast<const float4*>(A + (size_t)gm * KALL + kbase + k0 + ak);
            As[ak + 0][am] = v.x;
            As[ak + 1][am] = v.y;
            As[ak + 2][am] = v.z;
            As[ak + 3][am] = v.w;
        }
        {
            float4 v = *reinterpret_cast<const float4*>(
                Bm + (size_t)(kbase + k0 + bkk) * N + bn + bnn);
            *reinterpret_cast<float4*>(&Bs[bkk][bnn]) = v;
        }
        __syncthreads();
#pragma unroll
        for (int kk = 0; kk < 16; kk++) {
            float a[4], b[4];
#pragma unroll
            for (int i = 0; i < 4; i++) a[i] = As[kk][ty * 4 + i];
#pragma unroll
            for (int j = 0; j < 4; j++) b[j] = Bs[kk][tx * 4 + j];
#pragma unroll
            for (int i = 0; i < 4; i++)
#pragma unroll
                for (int j = 0; j < 4; j++) acc[i][j] = fmaf(a[i], b[j], acc[i][j]);
        }
        __syncthreads();
    }

    float* Cz = Cpart + (size_t)z * BB * N;
#pragma unroll
    for (int i = 0; i < 4; i++) {
        const int gm = bm + ty * 4 + i;
        if (gm >= BB) continue;
#pragma unroll
        for (int j = 0; j < 4; j++) {
            const int gn = bn + tx * 4 + j;
            Cz[(size_t)gm * N + gn] = acc[i][j];
        }
    }
}

// ---------------- big 128x128 tiled SGEMM (8x8 micro), no guards ----------
__global__ void gemm128_k(const float* __restrict__ A, const float* __restrict__ Bm,
                          const float* __restrict__ bias, float* __restrict__ C,
                          int M, int N, int K)
{
    __shared__ float As[8][128];
    __shared__ float Bs[8][128];
    const int bm = blockIdx.y * 128;
    const int bn = blockIdx.x * 128;
    const int tid = threadIdx.x;
    const int tx = tid & 15;
    const int ty = tid >> 4;

    float acc[8][8];
#pragma unroll
    for (int i = 0; i < 8; i++)
#pragma unroll
        for (int j = 0; j < 8; j++) acc[i][j] = 0.f;

    const int am = tid >> 1;
    const int ak = (tid & 1) * 4;
    const int bkk = tid >> 5;
    const int bn4 = (tid & 31) * 4;

    const float* Aptr = A + (size_t)(bm + am) * K + ak;
    const float* Bptr = Bm + (size_t)bkk * N + bn + bn4;

    for (int k0 = 0; k0 < K; k0 += 8) {
        float4 va = *reinterpret_cast<const float4*>(Aptr + k0);
        As[ak + 0][am] = va.x;
        As[ak + 1][am] = va.y;
        As[ak + 2][am] = va.z;
        As[ak + 3][am] = va.w;
        float4 vb = *reinterpret_cast<const float4*>(Bptr + (size_t)k0 * N);
        *reinterpret_cast<float4*>(&Bs[bkk][bn4]) = vb;
        __syncthreads();
#pragma unroll
        for (int kk = 0; kk < 8; kk++) {
            float a[8], b[8];
#pragma unroll
            for (int i = 0; i < 4; i++) {
                a[i]     = As[kk][ty * 4 + i];
                a[i + 4] = As[kk][64 + ty * 4 + i];
                b[i]     = Bs[kk][tx * 4 + i];
                b[i + 4] = Bs[kk][64 + tx * 4 + i];
            }
#pragma unroll
            for (int i = 0; i < 8; i++)
#pragma unroll
                for (int j = 0; j < 8; j++) acc[i][j] = fmaf(a[i], b[j], acc[i][j]);
        }
        __syncthreads();
    }

#pragma unroll
    for (int i = 0; i < 8; i++) {
        const int gm = bm + ((i < 4) ? (ty * 4 + i) : (64 + ty * 4 + i - 4));
#pragma unroll
        for (int j = 0; j < 8; j++) {
            const int gn = bn + ((j < 4) ? (tx * 4 + j) : (64 + tx * 4 + j - 4));
            C[(size_t)gm * N + gn] = acc[i][j] + bias[gn];
        }
    }
}

// ---------------- mean over P -------------------------------------------
__global__ void mean_k(const float* __restrict__ enc, float* __restrict__ out)
{
    const int blocksPerB = ENC / 256;
    const int b = blockIdx.x / blocksPerB;
    const int e = (blockIdx.x % blocksPerB) * 256 + threadIdx.x;
    const float* base = enc + (size_t)b * PP * ENC + e;
    float s = 0.f;
#pragma unroll 4
    for (int p = 0; p < PP; p++) s += base[(size_t)p * ENC];
    out[b * ENC + e] = s * (1.f / (float)PP);
}

// ---------------- fp32 -> fp16 convert -----------------------------------
__global__ void tohalf_k(const float* __restrict__ in, __half* __restrict__ out, size_t n2)
{
    const size_t i = (size_t)blockIdx.x * 256 + threadIdx.x;
    if (i >= n2) return;
    float2 v = reinterpret_cast<const float2*>(in)[i];
    reinterpret_cast<__half2*>(out)[i] = __floats2half2_rn(v.x, v.y);
}

// ---------------- weight packing [W_dec_att | W_fbeta | W_hh] ------------
__global__ void pack_k(const float* __restrict__ Wda, const float* __restrict__ Wfb,
                       const float* __restrict__ Whh, float* __restrict__ Wp)
{
    const int idx = blockIdx.x * 256 + threadIdx.x;
    if (idx >= DEC * HP) return;
    const int r = idx / HP;
    const int c = idx - r * HP;
    float v;
    if (c < OFF_FBETA)      v = Wda[r * ATT + c];
    else if (c < OFF_HH)    v = Wfb[r * ENC + (c - OFF_FBETA)];
    else                    v = Whh[r * (4 * DEC) + (c - OFF_HH)];
    Wp[idx] = v;
}
__global__ void packb_k(const float* __restrict__ bda, const float* __restrict__ bfb,
                        const float* __restrict__ bhh, float* __restrict__ bp)
{
    const int c = blockIdx.x * 256 + threadIdx.x;
    if (c >= HP) return;
    float v;
    if (c < OFF_FBETA)      v = bda[c];
    else if (c < OFF_HH)    v = bfb[c - OFF_FBETA];
    else                    v = bhh[c - OFF_HH];
    bp[c] = v;
}

// ---------------- gather embeddings for all timesteps --------------------
__global__ void gather_k(const int* __restrict__ captions, const float* __restrict__ emb,
                         float* __restrict__ out)
{
    const int idx = blockIdx.x * 256 + threadIdx.x;
    if (idx >= BB * TS * EMB) return;
    const int j = idx & (EMB - 1);
    const int row = idx >> 9;          // t*128 + b
    const int b = row & 127;
    const int t = row >> 7;
    const int cap = captions[b * TT + t];
    out[idx] = emb[(size_t)cap * EMB + j];
}

// ---------------- attention scores (fp16 encproj) ------------------------
__global__ void scores_k(const __half* __restrict__ encproj, const float* __restrict__ hproj,
                         const float* __restrict__ w_att, const float* __restrict__ b_att,
                         float* __restrict__ scores)
{
    const int bp = blockIdx.x;
    const int b = bp / PP;
    const __half* ep = encproj + (size_t)bp * ATT;
    const float* dp = hproj + (size_t)b * HP;
    const int a0 = threadIdx.x * 4;
    float s = 0.f;
    __half2 e01 = *reinterpret_cast<const __half2*>(ep + a0);
    __half2 e23 = *reinterpret_cast<const __half2*>(ep + a0 + 2);
    float4 d = *reinterpret_cast<const float4*>(dp + a0);
    float4 w = *reinterpret_cast<const float4*>(w_att + a0);
    s += w.x * fmaxf(__low2float(e01)  + d.x, 0.f);
    s += w.y * fmaxf(__high2float(e01) + d.y, 0.f);
    s += w.z * fmaxf(__low2float(e23)  + d.z, 0.f);
    s += w.w * fmaxf(__high2float(e23) + d.w, 0.f);
#pragma unroll
    for (int o = 16; o > 0; o >>= 1) s += __shfl_down_sync(0xffffffffu, s, o);
    __shared__ float ws[4];
    if ((threadIdx.x & 31) == 0) ws[threadIdx.x >> 5] = s;
    __syncthreads();
    if (threadIdx.x == 0) scores[bp] = ws[0] + ws[1] + ws[2] + ws[3] + b_att[0];
}

// ---------------- softmax over P ----------------------------------------
__global__ void softmax_k(const float* __restrict__ scores, float* __restrict__ alpha)
{
    const int b = blockIdx.x;
    const int t = threadIdx.x;
    __shared__ float red[256];
    float v = (t < PP) ? scores[b * PP + t] : -1e30f;
    red[t] = v;
    __syncthreads();
    for (int s = 128; s > 0; s >>= 1) {
        if (t < s) red[t] = fmaxf(red[t], red[t + s]);
        __syncthreads();
    }
    const float mx = red[0];
    __syncthreads();
    float e = (t < PP) ? expf(v - mx) : 0.f;
    red[t] = e;
    __syncthreads();
    for (int s = 128; s > 0; s >>= 1) {
        if (t < s) red[t] += red[t + s];
        __syncthreads();
    }
    const float sum = red[0];
    if (t < PP) alpha[b * PP + t] = e / sum;
}

// ---------------- context = alpha @ enc_out (fp16 enc) -------------------
__global__ void contexth_k(const float* __restrict__ alpha, const __half* __restrict__ enc,
                           float* __restrict__ ctx)
{
    const int blocksPerB = ENC / 512;
    const int b = blockIdx.x / blocksPerB;
    const int e = ((blockIdx.x % blocksPerB) * 256 + threadIdx.x) * 2;
    __shared__ float al[PP];
    for (int p = threadIdx.x; p < PP; p += 256) al[p] = alpha[b * PP + p];
    __syncthreads();
    const __half* base = enc + (size_t)b * PP * ENC + e;
    float s0 = 0.f, s1 = 0.f;
#pragma unroll 4
    for (int p = 0; p < PP; p++) {
        __half2 v = *reinterpret_cast<const __half2*>(base + (size_t)p * ENC);
        s0 = fmaf(al[p], __low2float(v), s0);
        s1 = fmaf(al[p], __high2float(v), s1);
    }
    ctx[b * ENC + e]     = s0;
    ctx[b * ENC + e + 1] = s1;
}

// ---------------- xc = sigmoid(fbeta) * context --------------------------
__global__ void gatex_k(const float* __restrict__ hproj, const float* __restrict__ ctx,
                        float* __restrict__ xc)
{
    const int idx = blockIdx.x * 256 + threadIdx.x;
    if (idx >= BB * ENC) return;
    const int b = idx >> 11;
    const int e = idx & (ENC - 1);
    const float g = sigmf(hproj[(size_t)b * HP + OFF_FBETA + e]);
    xc[idx] = g * ctx[idx];
}

// ---------------- fused LSTM: sum gate sources + cell update -------------
__global__ void lstm2_k(const float* __restrict__ embproj, const float* __restrict__ hproj,
                        const float* __restrict__ part, float* __restrict__ h,
                        float* __restrict__ c, __half* __restrict__ hallh, int t)
{
    const int idx = blockIdx.x * 256 + threadIdx.x;
    if (idx >= BB * DEC) return;
    const int b = idx >> 9;
    const int j = idx & (DEC - 1);
    const float* ep = embproj + (size_t)(t * BB + b) * (4 * DEC);
    const float* hp = hproj + (size_t)b * HP + OFF_HH;
    const float* p0 = part + (size_t)b * (4 * DEC);
    const float* p1 = p0 + (size_t)BB * 4 * DEC;
    const float* p2 = p1 + (size_t)BB * 4 * DEC;
    const float* p3 = p2 + (size_t)BB * 4 * DEC;

    float gt[4];
#pragma unroll
    for (int q = 0; q < 4; q++) {
        const int col = j + q * DEC;
        gt[q] = ep[col] + hp[col] + p0[col] + p1[col] + p2[col] + p3[col];
    }
    const float cn = sigmf(gt[1]) * c[idx] + sigmf(gt[0]) * tanhf(gt[2]);
    const float hn = sigmf(gt[3]) * tanhf(cn);
    c[idx] = cn;
    h[idx] = hn;
    hallh[(size_t)(t * BB + b) * DEC + j] = __float2half(hn);
}

// =========================================================================
extern "C" void kernel_launch(void* const* d_in, const int* in_sizes, int n_in,
                              void* d_out, int out_size)
{
    const float* enc_out  = (const float*)d_in[0];
    const int*   captions = (const int*)d_in[1];
    const float* emb      = (const float*)d_in[2];
    const float* W_init_h = (const float*)d_in[3];
    const float* b_init_h = (const float*)d_in[4];
    const float* W_init_c = (const float*)d_in[5];
    const float* b_init_c = (const float*)d_in[6];
    const float* W_enc_att = (const float*)d_in[7];
    const float* b_enc_att = (const float*)d_in[8];
    const float* W_dec_att = (const float*)d_in[9];
    const float* b_dec_att = (const float*)d_in[10];
    const float* w_att    = (const float*)d_in[11];
    const float* b_att    = (const float*)d_in[12];
    const float* W_fbeta  = (const float*)d_in[13];
    const float* b_fbeta  = (const float*)d_in[14];
    const float* W_ih     = (const float*)d_in[15];
    const float* b_ih     = (const float*)d_in[16];
    const float* W_hh     = (const float*)d_in[17];
    const float* b_hh     = (const float*)d_in[18];
    const float* W_fc     = (const float*)d_in[19];
    const float* b_fc     = (const float*)d_in[20];
    float* out = (float*)d_out;

    float *p_mean, *p_h, *p_c, *p_hproj, *p_scores, *p_alpha, *p_context,
          *p_xc, *p_part, *p_Wpack, *p_bpack, *p_embs, *p_embproj;
    __half *p_ench, *p_encprojh, *p_hallh, *p_wencT, *p_wfcT;
    cudaGetSymbolAddress((void**)&p_mean, g_mean);
    cudaGetSymbolAddress((void**)&p_h, g_h);
    cudaGetSymbolAddress((void**)&p_c, g_c);
    cudaGetSymbolAddress((void**)&p_ench, g_enc_h);
    cudaGetSymbolAddress((void**)&p_encprojh, g_encproj_h);
    cudaGetSymbolAddress((void**)&p_hproj, g_hproj);
    cudaGetSymbolAddress((void**)&p_scores, g_scores);
    cudaGetSymbolAddress((void**)&p_alpha, g_alpha);
    cudaGetSymbolAddress((void**)&p_context, g_context);
    cudaGetSymbolAddress((void**)&p_xc, g_xc);
    cudaGetSymbolAddress((void**)&p_part, g_part);
    cudaGetSymbolAddress((void**)&p_Wpack, g_Wpack);
    cudaGetSymbolAddress((void**)&p_bpack, g_bpack);
    cudaGetSymbolAddress((void**)&p_embs, g_embs);
    cudaGetSymbolAddress((void**)&p_embproj, g_embproj);
    cudaGetSymbolAddress((void**)&p_hallh, g_hall_h);
    cudaGetSymbolAddress((void**)&p_wencT, g_wencT);
    cudaGetSymbolAddress((void**)&p_wfcT, g_wfcT);

    const float* W_ih_bot = W_ih + (size_t)EMB * (4 * DEC);

    // ================= precompute (off critical path) =================
    mean_k<<<BB * (ENC / 256), 256>>>(enc_out, p_mean);
    {
        dim3 g((DEC + 63) / 64, (BB + 63) / 64);
        gemm64_k<0, 0><<<g, 256>>>(p_mean, W_init_h, b_init_h, p_h, BB, DEC, ENC, DEC);
        gemm64_k<0, 0><<<g, 256>>>(p_mean, W_init_c, b_init_c, p_c, BB, DEC, ENC, DEC);
    }
    // fp16 copy of enc_out
    {
        size_t n2 = (size_t)BB * PP * ENC / 2;
        tohalf_k<<<(unsigned)((n2 + 255) / 256), 256>>>(enc_out, p_ench, n2);
    }
    // transposed fp16 weights for HMMA GEMMs
    {
        dim3 g((ATT + 31) / 32, (ENC + 31) / 32);
        transh_k<<<g, 256>>>(W_enc_att, p_wencT, ENC, ATT, ATT);
    }
    {
        dim3 g((VPAD + 31) / 32, (DEC + 31) / 32);
        transh_k<<<g, 256>>>(W_fc, p_wfcT, DEC, VV, VPAD);
    }
    // pack h-projection weights
    pack_k<<<(DEC * HP + 255) / 256, 256>>>(W_dec_att, W_fbeta, W_hh, p_Wpack);
    packb_k<<<(HP + 255) / 256, 256>>>(b_dec_att, b_fbeta, b_hh, p_bpack);
    // gather embeddings, project all timesteps
    gather_k<<<(BB * TS * EMB + 255) / 256, 256>>>(captions, emb, p_embs);
    {
        dim3 g((4 * DEC) / 128, (BB * TS) / 128);
        gemm128_k<<<g, 256>>>(p_embs, W_ih, b_ih, p_embproj, BB * TS, 4 * DEC, EMB);
    }
    // enc_proj (fp16 out) via HMMA: [25088,512] = enc_h @ wencT^T
    {
        dim3 g(ATT / 128, (BB * PP) / 128);
        hgemm_k<32, 0><<<g, 256>>>(p_ench, ENC, p_wencT, ENC,
                                   b_enc_att, nullptr, p_encprojh, ATT);
    }

    // ================= recurrent loop (critical path) =================
    for (int t = 0; t < TS; t++) {
        {
            dim3 g(HP / 64, BB / 64);
            gemm64_k<0, 0><<<g, 256>>>(p_h, p_Wpack, p_bpack, p_hproj,
                                       BB, HP, DEC, HP);
        }
        scores_k<<<BB * PP, 128>>>(p_encprojh, p_hproj, w_att, b_att, p_scores);
        softmax_k<<<BB, 256>>>(p_scores, p_alpha);
        contexth_k<<<BB * (ENC / 512), 256>>>(p_alpha, p_ench, p_context);
        gatex_k<<<(BB * ENC + 255) / 256, 256>>>(p_hproj, p_context, p_xc);
        {
            dim3 g((4 * DEC) / 64, BB / 64, 4);
            gemm64_kz<<<g, 256>>>(p_xc, W_ih_bot, p_part);
        }
        lstm2_k<<<(BB * DEC + 255) / 256, 256>>>(p_embproj, p_hproj, p_part,
                                                 p_h, p_c, p_hallh, t);
    }

    // ================= final output GEMM via HMMA =================
    // out[b][t][:] = hall[t*128+b] @ W_fc + b_fc   (OMAP store, N guard)
    {
        dim3 g(VPAD / 128, (BB * TS) / 128);
        hgemm_k<8, 1><<<g, 256>>>(p_hallh, DEC, p_wfcT, DEC,
                                  b_fc, out, nullptr, VV);
    }
}

// round 17
// speedup vs baseline: 4.4159x; 1.5059x over previous
#include <cuda_runtime.h>
#include <cuda_fp16.h>
#include <math.h>
#include <stdint.h>

#define BB   128
#define PP   196
#define ENC  2048
#define EMB  512
#define DEC  512
#define ATT  512
#define VV   10000
#define VPAD 10112   // 79 * 128
#define TT   20
#define TS   19      // T-1
#define HP   4608    // packed h-proj width: 512 (dec_att) + 2048 (fbeta) + 2048 (hh)
#define OFF_FBETA 512
#define OFF_HH    2560

// ---------------- scratch (device globals, no allocation) ----------------
__device__ float  g_mean[BB * ENC];
__device__ float  g_h[BB * DEC];
__device__ float  g_c[BB * DEC];
__device__ __half g_h_h[BB * DEC];                       // fp16 h (recurrent)
__device__ __half g_enc_h[(size_t)BB * PP * ENC];        // fp16 enc_out
__device__ __half g_encproj_h[(size_t)BB * PP * ATT];    // fp16 enc_proj
__device__ float  g_hproj[BB * HP];                      // [dproj|fbeta|hh]
__device__ float  g_alpha[BB * PP];
__device__ __half g_xc_h[BB * ENC];                      // fp16 gate*context
__device__ float  g_part[4 * BB * 4 * DEC];              // split-K partials
__device__ float  g_Wpack[DEC * HP];
__device__ float  g_bpack[HP];
__device__ __half g_wpackT[(size_t)HP * DEC];            // Wpack^T fp16 [4608,512]
__device__ __half g_wihbT[(size_t)(4 * DEC) * ENC];      // W_ih_bot^T fp16 [2048,2048]
__device__ float  g_embs[BB * TS * EMB];                 // gathered embeddings
__device__ float  g_embproj[(size_t)BB * TS * 4 * DEC];  // emb @ W_ih_top + b_ih
__device__ __half g_hall_h[(size_t)BB * TS * DEC];       // all h_t fp16, row = t*128+b
__device__ __half g_wencT[(size_t)ATT * ENC];            // W_enc_att^T fp16 [512,2048]
__device__ __half g_wfcT[(size_t)VPAD * DEC];            // W_fc^T fp16 padded [10112,512]

__device__ __forceinline__ float sigmf(float x) { return 1.f / (1.f + expf(-x)); }

// ---------------- warp MMA m16n8k16 fp16->fp32 ---------------------------
__device__ __forceinline__ void mma16816(float* c, uint32_t a0, uint32_t a1,
                                         uint32_t a2, uint32_t a3,
                                         uint32_t b0, uint32_t b1)
{
    asm volatile(
        "mma.sync.aligned.m16n8k16.row.col.f32.f16.f16.f32 "
        "{%0,%1,%2,%3}, {%4,%5,%6,%7}, {%8,%9}, {%0,%1,%2,%3};"
        : "+f"(c[0]), "+f"(c[1]), "+f"(c[2]), "+f"(c[3])
        : "r"(a0), "r"(a1), "r"(a2), "r"(a3), "r"(b0), "r"(b1));
}

// ================= HMMA fp16 GEMM: D = A @ Bt^T (+ bias) =================
// A [M,K] fp16 K-major (lda), Bt [N,K] fp16 K-major (ldb). Tile 128x128,
// K = NC*64. 8 warps (4Mx2N), each 32x64 via 2x8 m16n8k16 fragments.
// OUTMODE 0: fp16 row-major store to Ch (+bias).
// OUTMODE 1: fp32 OMAP store ((gm&127)*TS + (gm>>7)) (+bias), guard gn<VV.
// OUTMODE 2: fp32 plain row-major store (+bias unless SPLITZ).
// SPLITZ 1: blockIdx.z selects K-slab of 512 (A,Bt col offset) and output
//           slab Cf + z*BB*ldc; no bias.
template <int NC, int OUTMODE, int SPLITZ>
__global__ void __launch_bounds__(256) hgemm_k(
    const __half* __restrict__ A, int lda,
    const __half* __restrict__ Bt, int ldb,
    const float* __restrict__ bias,
    float* __restrict__ Cf, __half* __restrict__ Ch, int ldc)
{
    __shared__ __half As[128 * 64];
    __shared__ __half Bs[128 * 64];
    char* Abuf = (char*)As;
    char* Bbuf = (char*)Bs;

    const int tid = threadIdx.x;
    const int bm = blockIdx.y * 128;
    const int bn = blockIdx.x * 128;
    if (SPLITZ) {
        const int zoff = blockIdx.z * 512;
        A += zoff;
        Bt += zoff;
        Cf += (size_t)blockIdx.z * BB * ldc;
    }
    const int lane = tid & 31, wid = tid >> 5;
    const int wm = wid & 3, wn = wid >> 2;        // 4 x 2 warp grid
    const int g = lane >> 2, tig = lane & 3;

    float acc[2][8][4];
#pragma unroll
    for (int mi = 0; mi < 2; mi++)
#pragma unroll
        for (int ni = 0; ni < 8; ni++)
#pragma unroll
            for (int q = 0; q < 4; q++) acc[mi][ni][q] = 0.f;

    // gmem copy mapping: 1024 uint4 per 16KB tile, 4 per thread
    const int row0 = tid >> 3, slot = tid & 7;    // rows step 32 per i
    const __half* Ab = A + (size_t)(bm + row0) * lda + slot * 8;
    const __half* Bb = Bt + (size_t)(bn + row0) * ldb + slot * 8;

    uint4 ar[4], br[4];
#pragma unroll
    for (int i = 0; i < 4; i++) {
        ar[i] = *(const uint4*)(Ab + (size_t)(i * 32) * lda);
        br[i] = *(const uint4*)(Bb + (size_t)(i * 32) * ldb);
    }

    for (int k = 0; k < NC; k++) {
        if (k) __syncthreads();
#pragma unroll
        for (int i = 0; i < 4; i++) {
            const uint32_t off = (row0 + i * 32) * 128 + slot * 16;
            const uint32_t sw = off ^ ((off >> 3) & 0x70);
            *(uint4*)(Abuf + sw) = ar[i];
            *(uint4*)(Bbuf + sw) = br[i];
        }
        __syncthreads();
        if (k + 1 < NC) {
#pragma unroll
            for (int i = 0; i < 4; i++) {
                ar[i] = *(const uint4*)(Ab + (size_t)(k + 1) * 64 + (size_t)(i * 32) * lda);
                br[i] = *(const uint4*)(Bb + (size_t)(k + 1) * 64 + (size_t)(i * 32) * ldb);
            }
        }
#pragma unroll
        for (int kk = 0; kk < 4; kk++) {
            uint32_t af[2][4];
#pragma unroll
            for (int mi = 0; mi < 2; mi++) {
                const int r0 = wm * 32 + mi * 16 + g;
                const int r1 = r0 + 8;
                const uint32_t c0 = kk * 32 + 4 * tig;
                const uint32_t c1 = c0 + 16;
                af[mi][0] = *(const uint32_t*)(Abuf + r0 * 128 + (c0 ^ ((r0 & 7) << 4)));
                af[mi][1] = *(const uint32_t*)(Abuf + r1 * 128 + (c0 ^ ((r1 & 7) << 4)));
                af[mi][2] = *(const uint32_t*)(Abuf + r0 * 128 + (c1 ^ ((r0 & 7) << 4)));
                af[mi][3] = *(const uint32_t*)(Abuf + r1 * 128 + (c1 ^ ((r1 & 7) << 4)));
            }
#pragma unroll
            for (int ni = 0; ni < 8; ni++) {
                const int n = wn * 64 + ni * 8 + g;
                const uint32_t kb0 = kk * 32 + 4 * tig;
                const uint32_t b0 = *(const uint32_t*)(Bbuf + n * 128 + (kb0 ^ ((n & 7) << 4)));
                const uint32_t b1 = *(const uint32_t*)(Bbuf + n * 128 + ((kb0 + 16) ^ ((n & 7) << 4)));
                mma16816(acc[0][ni], af[0][0], af[0][1], af[0][2], af[0][3], b0, b1);
                mma16816(acc[1][ni], af[1][0], af[1][1], af[1][2], af[1][3], b0, b1);
            }
        }
    }

    // epilogue
#pragma unroll
    for (int mi = 0; mi < 2; mi++) {
        const int gm0 = bm + wm * 32 + mi * 16 + g;
        const int gm1 = gm0 + 8;
#pragma unroll
        for (int ni = 0; ni < 8; ni++) {
            const int gn = bn + wn * 64 + ni * 8 + 2 * tig;
            const float bz0 = SPLITZ ? 0.f : bias[gn];
            const float bz1 = SPLITZ ? 0.f : bias[gn + 1];
            if (OUTMODE == 0) {
                *(__half2*)(Ch + (size_t)gm0 * ldc + gn) =
                    __floats2half2_rn(acc[mi][ni][0] + bz0, acc[mi][ni][1] + bz1);
                *(__half2*)(Ch + (size_t)gm1 * ldc + gn) =
                    __floats2half2_rn(acc[mi][ni][2] + bz0, acc[mi][ni][3] + bz1);
            } else if (OUTMODE == 1) {
                const size_t ro0 = (size_t)((gm0 & 127) * TS + (gm0 >> 7)) * ldc;
                const size_t ro1 = (size_t)((gm1 & 127) * TS + (gm1 >> 7)) * ldc;
                if (gn < VV)     Cf[ro0 + gn]     = acc[mi][ni][0] + bz0;
                if (gn + 1 < VV) Cf[ro0 + gn + 1] = acc[mi][ni][1] + bz1;
                if (gn < VV)     Cf[ro1 + gn]     = acc[mi][ni][2] + bz0;
                if (gn + 1 < VV) Cf[ro1 + gn + 1] = acc[mi][ni][3] + bz1;
            } else {
                Cf[(size_t)gm0 * ldc + gn]     = acc[mi][ni][0] + bz0;
                Cf[(size_t)gm0 * ldc + gn + 1] = acc[mi][ni][1] + bz1;
                Cf[(size_t)gm1 * ldc + gn]     = acc[mi][ni][2] + bz0;
                Cf[(size_t)gm1 * ldc + gn + 1] = acc[mi][ni][3] + bz1;
            }
        }
    }
}

// ---------------- transpose fp32 [K,N] -> fp16 [Npad,K], zero-padded ------
__global__ void transh_k(const float* __restrict__ src, __half* __restrict__ dst,
                         int K, int N, int Npad)
{
    __shared__ float t[32][33];
    const int n0 = blockIdx.x * 32, k0 = blockIdx.y * 32;
    const int x = threadIdx.x & 31, y = threadIdx.x >> 5;   // 256 thr: y 0..7
#pragma unroll
    for (int dy = 0; dy < 32; dy += 8) {
        const int k = k0 + y + dy, n = n0 + x;
        t[y + dy][x] = (k < K && n < N) ? src[(size_t)k * N + n] : 0.f;
    }
    __syncthreads();
#pragma unroll
    for (int dy = 0; dy < 32; dy += 8) {
        const int n = n0 + y + dy, k = k0 + x;
        if (n < Npad && k < K) dst[(size_t)n * K + k] = __float2half(t[x][y + dy]);
    }
}

// ---------------- generic 64x64 tiled SGEMM (4x4 micro), guarded ----------
template <int ACT, int ACCUM>
__global__ void gemm64_k(const float* __restrict__ A, const float* __restrict__ Bm,
                         const float* __restrict__ bias, float* __restrict__ C,
                         int M, int N, int K, int ldc)
{
    __shared__ float As[16][64];
    __shared__ float Bs[16][64];
    const int bm = blockIdx.y * 64;
    const int bn = blockIdx.x * 64;
    const int tid = threadIdx.x;
    const int tx = tid & 15;
    const int ty = tid >> 4;

    float acc[4][4];
#pragma unroll
    for (int i = 0; i < 4; i++)
#pragma unroll
        for (int j = 0; j < 4; j++) acc[i][j] = 0.f;

    const int am = tid >> 2;
    const int ak = (tid & 3) * 4;
    const int bkk = tid >> 4;
    const int bnn = (tid & 15) * 4;

    for (int k0 = 0; k0 < K; k0 += 16) {
        {
            const int gm = bm + am;
            float4 v = make_float4(0.f, 0.f, 0.f, 0.f);
            if (gm < M)
                v = *reinterpret_cast<const float4*>(A + (size_t)gm * K + k0 + ak);
            As[ak + 0][am] = v.x;
            As[ak + 1][am] = v.y;
            As[ak + 2][am] = v.z;
            As[ak + 3][am] = v.w;
        }
        {
            const int gn = bn + bnn;
            float4 v;
            if (gn + 3 < N) {
                v = *reinterpret_cast<const float4*>(Bm + (size_t)(k0 + bkk) * N + gn);
            } else {
                float t0 = (gn + 0 < N) ? Bm[(size_t)(k0 + bkk) * N + gn + 0] : 0.f;
                float t1 = (gn + 1 < N) ? Bm[(size_t)(k0 + bkk) * N + gn + 1] : 0.f;
                float t2 = (gn + 2 < N) ? Bm[(size_t)(k0 + bkk) * N + gn + 2] : 0.f;
                float t3 = (gn + 3 < N) ? Bm[(size_t)(k0 + bkk) * N + gn + 3] : 0.f;
                v = make_float4(t0, t1, t2, t3);
            }
            *reinterpret_cast<float4*>(&Bs[bkk][bnn]) = v;
        }
        __syncthreads();
#pragma unroll
        for (int kk = 0; kk < 16; kk++) {
            float a[4], b[4];
#pragma unroll
            for (int i = 0; i < 4; i++) a[i] = As[kk][ty * 4 + i];
#pragma unroll
            for (int j = 0; j < 4; j++) b[j] = Bs[kk][tx * 4 + j];
#pragma unroll
            for (int i = 0; i < 4; i++)
#pragma unroll
                for (int j = 0; j < 4; j++) acc[i][j] = fmaf(a[i], b[j], acc[i][j]);
        }
        __syncthreads();
    }

#pragma unroll
    for (int i = 0; i < 4; i++) {
        const int gm = bm + ty * 4 + i;
        if (gm >= M) continue;
        const size_t rowoff = (size_t)gm * ldc;
#pragma unroll
        for (int j = 0; j < 4; j++) {
            const int gn = bn + tx * 4 + j;
            if (gn >= N) continue;
            float v = acc[i][j] + bias[gn];
            if (ACCUM) v += C[rowoff + gn];
            if (ACT == 1) v = sigmf(v);
            C[rowoff + gn] = v;
        }
    }
}

// ---------------- big 128x128 tiled SGEMM (8x8 micro), no guards ----------
__global__ void gemm128_k(const float* __restrict__ A, const float* __restrict__ Bm,
                          const float* __restrict__ bias, float* __restrict__ C,
                          int M, int N, int K)
{
    __shared__ float As[8][128];
    __shared__ float Bs[8][128];
    const int bm = blockIdx.y * 128;
    const int bn = blockIdx.x * 128;
    const int tid = threadIdx.x;
    const int tx = tid & 15;
    const int ty = tid >> 4;

    float acc[8][8];
#pragma unroll
    for (int i = 0; i < 8; i++)
#pragma unroll
        for (int j = 0; j < 8; j++) acc[i][j] = 0.f;

    const int am = tid >> 1;
    const int ak = (tid & 1) * 4;
    const int bkk = tid >> 5;
    const int bn4 = (tid & 31) * 4;

    const float* Aptr = A + (size_t)(bm + am) * K + ak;
    const float* Bptr = Bm + (size_t)bkk * N + bn + bn4;

    for (int k0 = 0; k0 < K; k0 += 8) {
        float4 va = *reinterpret_cast<const float4*>(Aptr + k0);
        As[ak + 0][am] = va.x;
        As[ak + 1][am] = va.y;
        As[ak + 2][am] = va.z;
        As[ak + 3][am] = va.w;
        float4 vb = *reinterpret_cast<const float4*>(Bptr + (size_t)k0 * N);
        *reinterpret_cast<float4*>(&Bs[bkk][bn4]) = vb;
        __syncthreads();
#pragma unroll
        for (int kk = 0; kk < 8; kk++) {
            float a[8], b[8];
#pragma unroll
            for (int i = 0; i < 4; i++) {
                a[i]     = As[kk][ty * 4 + i];
                a[i + 4] = As[kk][64 + ty * 4 + i];
                b[i]     = Bs[kk][tx * 4 + i];
                b[i + 4] = Bs[kk][64 + tx * 4 + i];
            }
#pragma unroll
            for (int i = 0; i < 8; i++)
#pragma unroll
                for (int j = 0; j < 8; j++) acc[i][j] = fmaf(a[i], b[j], acc[i][j]);
        }
        __syncthreads();
    }

#pragma unroll
    for (int i = 0; i < 8; i++) {
        const int gm = bm + ((i < 4) ? (ty * 4 + i) : (64 + ty * 4 + i - 4));
#pragma unroll
        for (int j = 0; j < 8; j++) {
            const int gn = bn + ((j < 4) ? (tx * 4 + j) : (64 + tx * 4 + j - 4));
            C[(size_t)gm * N + gn] = acc[i][j] + bias[gn];
        }
    }
}

// ---------------- mean over P -------------------------------------------
__global__ void mean_k(const float* __restrict__ enc, float* __restrict__ out)
{
    const int blocksPerB = ENC / 256;
    const int b = blockIdx.x / blocksPerB;
    const int e = (blockIdx.x % blocksPerB) * 256 + threadIdx.x;
    const float* base = enc + (size_t)b * PP * ENC + e;
    float s = 0.f;
#pragma unroll 4
    for (int p = 0; p < PP; p++) s += base[(size_t)p * ENC];
    out[b * ENC + e] = s * (1.f / (float)PP);
}

// ---------------- fp32 -> fp16 convert -----------------------------------
__global__ void tohalf_k(const float* __restrict__ in, __half* __restrict__ out, size_t n2)
{
    const size_t i = (size_t)blockIdx.x * 256 + threadIdx.x;
    if (i >= n2) return;
    float2 v = reinterpret_cast<const float2*>(in)[i];
    reinterpret_cast<__half2*>(out)[i] = __floats2half2_rn(v.x, v.y);
}

// ---------------- weight packing [W_dec_att | W_fbeta | W_hh] ------------
__global__ void pack_k(const float* __restrict__ Wda, const float* __restrict__ Wfb,
                       const float* __restrict__ Whh, float* __restrict__ Wp)
{
    const int idx = blockIdx.x * 256 + threadIdx.x;
    if (idx >= DEC * HP) return;
    const int r = idx / HP;
    const int c = idx - r * HP;
    float v;
    if (c < OFF_FBETA)      v = Wda[r * ATT + c];
    else if (c < OFF_HH)    v = Wfb[r * ENC + (c - OFF_FBETA)];
    else                    v = Whh[r * (4 * DEC) + (c - OFF_HH)];
    Wp[idx] = v;
}
__global__ void packb_k(const float* __restrict__ bda, const float* __restrict__ bfb,
                        const float* __restrict__ bhh, float* __restrict__ bp)
{
    const int c = blockIdx.x * 256 + threadIdx.x;
    if (c >= HP) return;
    float v;
    if (c < OFF_FBETA)      v = bda[c];
    else if (c < OFF_HH)    v = bfb[c - OFF_FBETA];
    else                    v = bhh[c - OFF_HH];
    bp[c] = v;
}

// ---------------- gather embeddings for all timesteps --------------------
__global__ void gather_k(const int* __restrict__ captions, const float* __restrict__ emb,
                         float* __restrict__ out)
{
    const int idx = blockIdx.x * 256 + threadIdx.x;
    if (idx >= BB * TS * EMB) return;
    const int j = idx & (EMB - 1);
    const int row = idx >> 9;          // t*128 + b
    const int b = row & 127;
    const int t = row >> 7;
    const int cap = captions[b * TT + t];
    out[idx] = emb[(size_t)cap * EMB + j];
}

// ---------------- h fp32 -> fp16 ----------------------------------------
__global__ void h2h_k(const float* __restrict__ h, __half* __restrict__ hh)
{
    const int i = blockIdx.x * 256 + threadIdx.x;
    if (i < BB * DEC) hh[i] = __float2half(h[i]);
}

// ---------------- fused scores + softmax --------------------------------
// grid = BB, 256 threads (8 warps). Warp w handles pixels p = w, w+8, ...
// Each pixel row: ATT=512 halves = 256 half2; 32 lanes x 8 half2 each.
__global__ void __launch_bounds__(256) scoresmax_k(
    const __half* __restrict__ encproj, const float* __restrict__ hproj,
    const float* __restrict__ w_att, const float* __restrict__ b_att,
    float* __restrict__ alpha)
{
    const int b = blockIdx.x;
    const int tid = threadIdx.x;
    const int lane = tid & 31, w = tid >> 5;
    __shared__ float2 swd[ATT];          // (w_att, dproj) pairs
    __shared__ float sc[256];
    __shared__ float red[256];

    for (int i = tid; i < ATT; i += 256)
        swd[i] = make_float2(w_att[i], hproj[(size_t)b * HP + i]);
    sc[tid] = -1e30f;
    __syncthreads();

    const float batt = b_att[0];
    for (int p = w; p < PP; p += 8) {
        const __half2* row = (const __half2*)(encproj + ((size_t)b * PP + p) * ATT);
        float s = 0.f;
#pragma unroll
        for (int j = 0; j < 8; j++) {            // 256 half2 / 32 lanes
            const int idx = lane + 32 * j;       // half2 index in [0,256)
            const __half2 h2 = row[idx];
            const float4 q = *(const float4*)&swd[2 * idx];   // pairs 2idx, 2idx+1
            s += q.x * fmaxf(__low2float(h2) + q.y, 0.f);
            s += q.z * fmaxf(__high2float(h2) + q.w, 0.f);
        }
#pragma unroll
        for (int o = 16; o > 0; o >>= 1) s += __shfl_down_sync(0xffffffffu, s, o);
        if (lane == 0) sc[p] = s + batt;
    }
    __syncthreads();

    const float v = sc[tid];
    red[tid] = v;
    __syncthreads();
    for (int s2 = 128; s2 > 0; s2 >>= 1) {
        if (tid < s2) red[tid] = fmaxf(red[tid], red[tid + s2]);
        __syncthreads();
    }
    const float mx = red[0];
    __syncthreads();
    const float e = (tid < PP) ? expf(v - mx) : 0.f;
    red[tid] = e;
    __syncthreads();
    for (int s2 = 128; s2 > 0; s2 >>= 1) {
        if (tid < s2) red[tid] += red[tid + s2];
        __syncthreads();
    }
    if (tid < PP) alpha[b * PP + tid] = e / red[0];
}

// ---------------- fused context + gate: xc = sigmoid(fbeta)*ctx (fp16) ---
__global__ void ctxgate_k(const float* __restrict__ alpha, const __half* __restrict__ enc,
                          const float* __restrict__ hproj, __half* __restrict__ xch)
{
    const int blocksPerB = ENC / 512;                  // 4
    const int b = blockIdx.x / blocksPerB;
    const int e = ((blockIdx.x % blocksPerB) * 256 + threadIdx.x) * 2;
    __shared__ float al[PP];
    for (int p = threadIdx.x; p < PP; p += 256) al[p] = alpha[b * PP + p];
    __syncthreads();
    const __half* base = enc + (size_t)b * PP * ENC + e;
    float s0 = 0.f, s1 = 0.f;
#pragma unroll 4
    for (int p = 0; p < PP; p++) {
        const __half2 v = *(const __half2*)(base + (size_t)p * ENC);
        s0 = fmaf(al[p], __low2float(v), s0);
        s1 = fmaf(al[p], __high2float(v), s1);
    }
    const float g0 = sigmf(hproj[(size_t)b * HP + OFF_FBETA + e]);
    const float g1 = sigmf(hproj[(size_t)b * HP + OFF_FBETA + e + 1]);
    *(__half2*)(xch + (size_t)b * ENC + e) = __floats2half2_rn(g0 * s0, g1 * s1);
}

// ---------------- fused LSTM: sum gate sources + cell update -------------
__global__ void lstm2_k(const float* __restrict__ embproj, const float* __restrict__ hproj,
                        const float* __restrict__ part, __half* __restrict__ hh,
                        float* __restrict__ c, __half* __restrict__ hallh, int t)
{
    const int idx = blockIdx.x * 256 + threadIdx.x;
    if (idx >= BB * DEC) return;
    const int b = idx >> 9;
    const int j = idx & (DEC - 1);
    const float* ep = embproj + (size_t)(t * BB + b) * (4 * DEC);
    const float* hp = hproj + (size_t)b * HP + OFF_HH;
    const float* p0 = part + (size_t)b * (4 * DEC);
    const float* p1 = p0 + (size_t)BB * 4 * DEC;
    const float* p2 = p1 + (size_t)BB * 4 * DEC;
    const float* p3 = p2 + (size_t)BB * 4 * DEC;

    float gt[4];
#pragma unroll
    for (int q = 0; q < 4; q++) {
        const int col = j + q * DEC;
        gt[q] = ep[col] + hp[col] + p0[col] + p1[col] + p2[col] + p3[col];
    }
    const float cn = sigmf(gt[1]) * c[idx] + sigmf(gt[0]) * tanhf(gt[2]);
    const float hn = sigmf(gt[3]) * tanhf(cn);
    c[idx] = cn;
    const __half hh16 = __float2half(hn);
    hh[idx] = hh16;
    hallh[(size_t)(t * BB + b) * DEC + j] = hh16;
}

// =========================================================================
extern "C" void kernel_launch(void* const* d_in, const int* in_sizes, int n_in,
                              void* d_out, int out_size)
{
    const float* enc_out  = (const float*)d_in[0];
    const int*   captions = (const int*)d_in[1];
    const float* emb      = (const float*)d_in[2];
    const float* W_init_h = (const float*)d_in[3];
    const float* b_init_h = (const float*)d_in[4];
    const float* W_init_c = (const float*)d_in[5];
    const float* b_init_c = (const float*)d_in[6];
    const float* W_enc_att = (const float*)d_in[7];
    const float* b_enc_att = (const float*)d_in[8];
    const float* W_dec_att = (const float*)d_in[9];
    const float* b_dec_att = (const float*)d_in[10];
    const float* w_att    = (const float*)d_in[11];
    const float* b_att    = (const float*)d_in[12];
    const float* W_fbeta  = (const float*)d_in[13];
    const float* b_fbeta  = (const float*)d_in[14];
    const float* W_ih     = (const float*)d_in[15];
    const float* b_ih     = (const float*)d_in[16];
    const float* W_hh     = (const float*)d_in[17];
    const float* b_hh     = (const float*)d_in[18];
    const float* W_fc     = (const float*)d_in[19];
    const float* b_fc     = (const float*)d_in[20];
    float* out = (float*)d_out;

    float *p_mean, *p_h, *p_c, *p_hproj, *p_alpha, *p_part, *p_Wpack,
          *p_bpack, *p_embs, *p_embproj;
    __half *p_ench, *p_encprojh, *p_hallh, *p_wencT, *p_wfcT, *p_hh,
           *p_xch, *p_wpackT, *p_wihbT;
    cudaGetSymbolAddress((void**)&p_mean, g_mean);
    cudaGetSymbolAddress((void**)&p_h, g_h);
    cudaGetSymbolAddress((void**)&p_c, g_c);
    cudaGetSymbolAddress((void**)&p_hh, g_h_h);
    cudaGetSymbolAddress((void**)&p_ench, g_enc_h);
    cudaGetSymbolAddress((void**)&p_encprojh, g_encproj_h);
    cudaGetSymbolAddress((void**)&p_hproj, g_hproj);
    cudaGetSymbolAddress((void**)&p_alpha, g_alpha);
    cudaGetSymbolAddress((void**)&p_xch, g_xc_h);
    cudaGetSymbolAddress((void**)&p_part, g_part);
    cudaGetSymbolAddress((void**)&p_Wpack, g_Wpack);
    cudaGetSymbolAddress((void**)&p_bpack, g_bpack);
    cudaGetSymbolAddress((void**)&p_wpackT, g_wpackT);
    cudaGetSymbolAddress((void**)&p_wihbT, g_wihbT);
    cudaGetSymbolAddress((void**)&p_embs, g_embs);
    cudaGetSymbolAddress((void**)&p_embproj, g_embproj);
    cudaGetSymbolAddress((void**)&p_hallh, g_hall_h);
    cudaGetSymbolAddress((void**)&p_wencT, g_wencT);
    cudaGetSymbolAddress((void**)&p_wfcT, g_wfcT);

    const float* W_ih_bot = W_ih + (size_t)EMB * (4 * DEC);

    // ================= precompute (off critical path) =================
    mean_k<<<BB * (ENC / 256), 256>>>(enc_out, p_mean);
    {
        dim3 g((DEC + 63) / 64, (BB + 63) / 64);
        gemm64_k<0, 0><<<g, 256>>>(p_mean, W_init_h, b_init_h, p_h, BB, DEC, ENC, DEC);
        gemm64_k<0, 0><<<g, 256>>>(p_mean, W_init_c, b_init_c, p_c, BB, DEC, ENC, DEC);
    }
    h2h_k<<<(BB * DEC + 255) / 256, 256>>>(p_h, p_hh);
    // fp16 copy of enc_out
    {
        size_t n2 = (size_t)BB * PP * ENC / 2;
        tohalf_k<<<(unsigned)((n2 + 255) / 256), 256>>>(enc_out, p_ench, n2);
    }
    // transposed fp16 weights for HMMA GEMMs
    {
        dim3 g((ATT + 31) / 32, (ENC + 31) / 32);
        transh_k<<<g, 256>>>(W_enc_att, p_wencT, ENC, ATT, ATT);
    }
    {
        dim3 g((VPAD + 31) / 32, (DEC + 31) / 32);
        transh_k<<<g, 256>>>(W_fc, p_wfcT, DEC, VV, VPAD);
    }
    {
        dim3 g((4 * DEC + 31) / 32, (ENC + 31) / 32);
        transh_k<<<g, 256>>>(W_ih_bot, p_wihbT, ENC, 4 * DEC, 4 * DEC);
    }
    // pack h-projection weights, then transpose to fp16
    pack_k<<<(DEC * HP + 255) / 256, 256>>>(W_dec_att, W_fbeta, W_hh, p_Wpack);
    packb_k<<<(HP + 255) / 256, 256>>>(b_dec_att, b_fbeta, b_hh, p_bpack);
    {
        dim3 g((HP + 31) / 32, (DEC + 31) / 32);
        transh_k<<<g, 256>>>(p_Wpack, p_wpackT, DEC, HP, HP);
    }
    // gather embeddings, project all timesteps
    gather_k<<<(BB * TS * EMB + 255) / 256, 256>>>(captions, emb, p_embs);
    {
        dim3 g((4 * DEC) / 128, (BB * TS) / 128);
        gemm128_k<<<g, 256>>>(p_embs, W_ih, b_ih, p_embproj, BB * TS, 4 * DEC, EMB);
    }
    // enc_proj (fp16 out) via HMMA: [25088,512] = enc_h @ wencT^T
    {
        dim3 g(ATT / 128, (BB * PP) / 128);
        hgemm_k<32, 0, 0><<<g, 256>>>(p_ench, ENC, p_wencT, ENC,
                                      b_enc_att, nullptr, p_encprojh, ATT);
    }

    // ================= recurrent loop (critical path) =================
    for (int t = 0; t < TS; t++) {
        // hproj = h_h @ WpackT^T + bpack  (fp32 out [128,4608])
        hgemm_k<8, 2, 0><<<dim3(HP / 128, 1), 256>>>(
            p_hh, DEC, p_wpackT, DEC, p_bpack, p_hproj, nullptr, HP);
        // fused scores + softmax
        scoresmax_k<<<BB, 256>>>(p_encprojh, p_hproj, w_att, b_att, p_alpha);
        // fused context + gate -> xc fp16
        ctxgate_k<<<BB * (ENC / 512), 256>>>(p_alpha, p_ench, p_hproj, p_xch);
        // xc @ W_ih_bot via HMMA split-K x4 -> fp32 partials
        hgemm_k<8, 2, 1><<<dim3((4 * DEC) / 128, 1, 4), 256>>>(
            p_xch, ENC, p_wihbT, ENC, nullptr, p_part, nullptr, 4 * DEC);
        // LSTM cell update (writes fp16 h + hall)
        lstm2_k<<<(BB * DEC + 255) / 256, 256>>>(p_embproj, p_hproj, p_part,
                                                 p_hh, p_c, p_hallh, t);
    }

    // ================= final output GEMM via HMMA =================
    // out[b][t][:] = hall[t*128+b] @ W_fc + b_fc   (OMAP store, N guard)
    {
        dim3 g(VPAD / 128, (BB * TS) / 128);
        hgemm_k<8, 1, 0><<<g, 256>>>(p_hallh, DEC, p_wfcT, DEC,
                                     b_fc, out, nullptr, VV);
    }
}